// round 13
// baseline (speedup 1.0000x reference)
#include <cuda_runtime.h>
#include <cuda_fp16.h>
#include <math.h>
#include <stdint.h>
#include <mma.h>

using namespace nvcuda;

#define BATCH 32
#define SEQ 197
#define DIM 768
#define NHEAD 12
#define DHEAD 64
#define NLAYER 12
#define MLPD 3072
#define NOUT 1000
#define NPATCH 196
#define MTOK (BATCH*SEQ)        /* 6304 */
#define MPAT (BATCH*NPATCH)     /* 6272 */
#define ASTRIDE 208             /* padded attn row stride */

// ---------------- scratch (device globals) ----------------------------------
__device__ float  g_tokens[MTOK*DIM];
__device__ float  g_embf[MPAT*DIM];
__device__ float  g_h[MTOK*DIM];
__device__ float  g_q[MTOK*DIM];
__device__ float  g_k[MTOK*DIM];
__device__ float  g_v[MTOK*DIM];
__device__ __half g_attnh[(size_t)BATCH*NHEAD*SEQ*ASTRIDE];
__device__ __half g_hh[MTOK*DIM];
__device__ __half g_mlph[(size_t)MTOK*MLPD];
__device__ __half g_ph[(size_t)MPAT*DIM];
__device__ __half g_w1t[(size_t)NLAYER*MLPD*DIM];   // [l][N=3072][K=768]
__device__ __half g_w2t[(size_t)NLAYER*DIM*MLPD];   // [l][N=768][K=3072]
__device__ __half g_wembt[DIM*DIM];                 // [N=768][K=768]

__device__ __forceinline__ float gelu_exact(float x) {
    return 0.5f * x * (1.f + erff(x * 0.70710678118654752f));
}
__device__ __forceinline__ float r32(float x) { return wmma::__float_to_tf32(x); }
__device__ __forceinline__ uint32_t s2u(const void* p) {
    uint32_t a;
    asm("{ .reg .u64 t; cvta.to.shared.u64 t, %1; cvt.u32.u64 %0, t; }" : "=r"(a) : "l"(p));
    return a;
}
__device__ __forceinline__ void cp16(uint32_t dst, const void* src, bool pred) {
    int sz = pred ? 16 : 0;
    asm volatile("cp.async.ca.shared.global [%0], [%1], 16, %2;"
                 :: "r"(dst), "l"(src), "r"(sz));
}
#define CP_COMMIT() asm volatile("cp.async.commit_group;" ::: "memory")
#define CP_WAIT0()  asm volatile("cp.async.wait_group 0;" ::: "memory")

// ================= fp16 wmma GEMM: 256 thr, 8 warps (2x4), warp 64x32 =======
// (verified R10)
#define GH_LDS 72
#define GH_BUF (128*GH_LDS)
#define GH_LDE 132
#define GH_SMEM_BYTES (4*GH_BUF*2 > 128*GH_LDE*4 ? 4*GH_BUF*2 : 128*GH_LDE*4)

template<int ACT, int OUTMODE>
__global__ void __launch_bounds__(256, 2)
gemm_h(int M, int K,
       const __half* __restrict__ A, int lda,
       const __half* __restrict__ Bt, int ldb,
       const float* __restrict__ bias,
       float* __restrict__ Cf, __half* __restrict__ Ch, int ldc) {
    extern __shared__ __align__(128) __half smh[];
    const int tid = threadIdx.x;
    const int wid = tid >> 5;
    const int row0 = blockIdx.y * 128, col0 = blockIdx.x * 128;
    const int wm = wid & 1, wn = wid >> 1;

    wmma::fragment<wmma::accumulator, 16, 16, 16, float> acc[4][2];
#pragma unroll
    for (int i = 0; i < 4; i++)
#pragma unroll
        for (int j = 0; j < 2; j++) wmma::fill_fragment(acc[i][j], 0.f);

    const int nc = K >> 6;
    const int r = tid >> 3, c = tid & 7;

    {   // stage 0
        __half* As = smh;
        __half* Bs = smh + 2*GH_BUF;
#pragma unroll
        for (int i = 0; i < 4; i++) {
            int rr = r + i * 32;
            cp16(s2u(&As[rr * GH_LDS + c * 8]),
                 A + (size_t)(row0 + rr) * lda + c * 8, (row0 + rr) < M);
            cp16(s2u(&Bs[rr * GH_LDS + c * 8]),
                 Bt + (size_t)(col0 + rr) * ldb + c * 8, true);
        }
        CP_COMMIT();
    }

    for (int kc = 0; kc < nc; kc++) {
        const int cur = kc & 1;
        CP_WAIT0();
        __syncthreads();
        if (kc + 1 < nc) {
            const int nxt = 1 - cur;
            const int ko = (kc + 1) * 64;
            __half* As = smh + nxt * GH_BUF;
            __half* Bs = smh + 2*GH_BUF + nxt * GH_BUF;
#pragma unroll
            for (int i = 0; i < 4; i++) {
                int rr = r + i * 32;
                cp16(s2u(&As[rr * GH_LDS + c * 8]),
                     A + (size_t)(row0 + rr) * lda + ko + c * 8, (row0 + rr) < M);
                cp16(s2u(&Bs[rr * GH_LDS + c * 8]),
                     Bt + (size_t)(col0 + rr) * ldb + ko + c * 8, true);
            }
            CP_COMMIT();
        }
        const __half* As = smh + cur * GH_BUF;
        const __half* Bs = smh + 2*GH_BUF + cur * GH_BUF;
#pragma unroll
        for (int ks = 0; ks < 4; ks++) {
            wmma::fragment<wmma::matrix_a, 16, 16, 16, __half, wmma::row_major> af[4];
#pragma unroll
            for (int i = 0; i < 4; i++)
                wmma::load_matrix_sync(af[i], &As[(wm*64 + i*16) * GH_LDS + ks*16], GH_LDS);
#pragma unroll
            for (int j = 0; j < 2; j++) {
                wmma::fragment<wmma::matrix_b, 16, 16, 16, __half, wmma::col_major> bf;
                wmma::load_matrix_sync(bf, &Bs[(wn*32 + j*16) * GH_LDS + ks*16], GH_LDS);
#pragma unroll
                for (int i = 0; i < 4; i++)
                    wmma::mma_sync(acc[i][j], af[i], bf, acc[i][j]);
            }
        }
    }

    __syncthreads();
    float* Epi = (float*)smh;
#pragma unroll
    for (int i = 0; i < 4; i++)
#pragma unroll
        for (int j = 0; j < 2; j++)
            wmma::store_matrix_sync(&Epi[(wm*64 + i*16) * GH_LDE + wn*32 + j*16],
                                    acc[i][j], GH_LDE, wmma::mem_row_major);
    __syncthreads();
#pragma unroll 4
    for (int it = 0; it < 16; it++) {
        int l = it * 256 + tid;
        int rr = l >> 5, c4 = l & 31;
        int gr = row0 + rr;
        if (gr >= M) continue;
        float4 v = *(float4*)&Epi[rr * GH_LDE + c4 * 4];
        int gc = col0 + c4 * 4;
        v.x += bias[gc+0]; v.y += bias[gc+1]; v.z += bias[gc+2]; v.w += bias[gc+3];
        if (ACT == 1) {
            v.x = gelu_exact(v.x); v.y = gelu_exact(v.y);
            v.z = gelu_exact(v.z); v.w = gelu_exact(v.w);
        }
        if (OUTMODE == 2) {
            __half2 h0 = __floats2half2_rn(v.x, v.y);
            __half2 h1 = __floats2half2_rn(v.z, v.w);
            uint2 pk = make_uint2(*(uint32_t*)&h0, *(uint32_t*)&h1);
            *(uint2*)(Ch + (size_t)gr * ldc + gc) = pk;
        } else {
            float* cp = Cf + (size_t)gr * ldc + gc;
            if (OUTMODE == 1) {
                float4 o = *(const float4*)cp;
                v.x += o.x; v.y += o.y; v.z += o.z; v.w += o.w;
            }
            *(float4*)cp = v;
        }
    }
}

// ---------------- QKV projection (wmma tf32, verified R10) ------------------
__global__ void __launch_bounds__(128)
k_qkv_tc(const float* __restrict__ wq, const float* __restrict__ wk,
         const float* __restrict__ wv, const float* __restrict__ bq,
         const float* __restrict__ bk, const float* __restrict__ bv, int l) {
    __shared__ float Hs[64][68];
    __shared__ float Ws[64][68];
    __shared__ float Epi[64][68];
    int head = blockIdx.y, which = blockIdx.z;
    const float* W; const float* bias; float* out;
    if (which == 0)      { W = wq; bias = bq; out = g_q; }
    else if (which == 1) { W = wk; bias = bk; out = g_k; }
    else                 { W = wv; bias = bv; out = g_v; }
    W    += ((size_t)l*NHEAD + head) * DHEAD * DHEAD;
    bias += ((size_t)l*NHEAD + head) * DHEAD;
    const int m0 = blockIdx.x * 64;
    const int tid = threadIdx.x, wid = tid >> 5;

#pragma unroll
    for (int i = 0; i < 8; i++) {
        int ll = i * 128 + tid;
        int rr = ll >> 4, c4 = ll & 15;
        float4 v = make_float4(0.f,0.f,0.f,0.f);
        if (m0 + rr < MTOK)
            v = *(const float4*)(g_h + (size_t)(m0 + rr)*DIM + head*DHEAD + c4*4);
        *(float4*)&Hs[rr][c4*4] = v;
        float4 w = *(const float4*)(W + rr*64 + c4*4);
        w.x = r32(w.x); w.y = r32(w.y); w.z = r32(w.z); w.w = r32(w.w);
        *(float4*)&Ws[rr][c4*4] = w;
    }
    __syncthreads();

    wmma::fragment<wmma::accumulator, 16, 16, 8, float> acc[4];
#pragma unroll
    for (int j = 0; j < 4; j++) wmma::fill_fragment(acc[j], 0.f);
#pragma unroll
    for (int ks = 0; ks < 8; ks++) {
        wmma::fragment<wmma::matrix_a, 16, 16, 8, wmma::precision::tf32, wmma::row_major> af;
        wmma::load_matrix_sync(af, &Hs[wid*16][ks*8], 68);
#pragma unroll
        for (int j = 0; j < 4; j++) {
            wmma::fragment<wmma::matrix_b, 16, 16, 8, wmma::precision::tf32, wmma::row_major> bf;
            wmma::load_matrix_sync(bf, &Ws[ks*8][j*16], 68);
            wmma::mma_sync(acc[j], af, bf, acc[j]);
        }
    }
#pragma unroll
    for (int j = 0; j < 4; j++)
        wmma::store_matrix_sync(&Epi[wid*16][j*16], acc[j], 68, wmma::mem_row_major);
    __syncthreads();
#pragma unroll
    for (int i = 0; i < 8; i++) {
        int ll = i * 128 + tid;
        int rr = ll >> 4, c4 = ll & 15;
        int gr = m0 + rr;
        if (gr >= MTOK) continue;
        float4 v = *(float4*)&Epi[rr][c4*4];
        v.x = r32(v.x + bias[c4*4+0]); v.y = r32(v.y + bias[c4*4+1]);
        v.z = r32(v.z + bias[c4*4+2]); v.w = r32(v.w + bias[c4*4+3]);
        *(float4*)(out + (size_t)gr*DIM + head*DHEAD + c4*4) = v;
    }
}

// ---------------- attention scores (tf32 compute, half storage) -------------
__global__ void __launch_bounds__(128)
k_scores_tc() {
    __shared__ float Qs[64][68];
    __shared__ float Ks[64][68];
    __shared__ float Epi[64][68];
    const int bz = blockIdx.z;
    const int b = bz / NHEAD, h = bz % NHEAD;
    const int t0 = blockIdx.x * 64, s0 = blockIdx.y * 64;
    const int tid = threadIdx.x, wid = tid >> 5;
    const float* Q = g_q + (size_t)b*SEQ*DIM + h*DHEAD;
    const float* K = g_k + (size_t)b*SEQ*DIM + h*DHEAD;

#pragma unroll
    for (int i = 0; i < 8; i++) {
        int ll = i * 128 + tid;
        int rr = ll >> 4, c4 = ll & 15;
        float4 q = make_float4(0.f,0.f,0.f,0.f);
        if (s0 + rr < SEQ) q = *(const float4*)(Q + (size_t)(s0 + rr)*DIM + c4*4);
        *(float4*)&Qs[rr][c4*4] = q;
        float4 k = make_float4(0.f,0.f,0.f,0.f);
        if (t0 + rr < SEQ) k = *(const float4*)(K + (size_t)(t0 + rr)*DIM + c4*4);
        *(float4*)&Ks[rr][c4*4] = k;
    }
    __syncthreads();

    wmma::fragment<wmma::accumulator, 16, 16, 8, float> acc[4];
#pragma unroll
    for (int j = 0; j < 4; j++) wmma::fill_fragment(acc[j], 0.f);
#pragma unroll
    for (int ks = 0; ks < 8; ks++) {
        wmma::fragment<wmma::matrix_a, 16, 16, 8, wmma::precision::tf32, wmma::row_major> af;
        wmma::load_matrix_sync(af, &Qs[wid*16][ks*8], 68);
#pragma unroll
        for (int j = 0; j < 4; j++) {
            wmma::fragment<wmma::matrix_b, 16, 16, 8, wmma::precision::tf32, wmma::col_major> bf;
            wmma::load_matrix_sync(bf, &Ks[j*16][ks*8], 68);
            wmma::mma_sync(acc[j], af, bf, acc[j]);
        }
    }
#pragma unroll
    for (int j = 0; j < 4; j++)
        wmma::store_matrix_sync(&Epi[wid*16][j*16], acc[j], 68, wmma::mem_row_major);
    __syncthreads();
#pragma unroll
    for (int i = 0; i < 8; i++) {
        int ll = i * 128 + tid;
        int rr = ll >> 4, c4 = ll & 15;
        int s = s0 + rr;
        if (s >= SEQ) continue;
        int t = t0 + c4*4;
        if (t >= ASTRIDE) continue;
        float4 v = *(float4*)&Epi[rr][c4*4];
        v.x *= 0.125f; v.y *= 0.125f; v.z *= 0.125f; v.w *= 0.125f;
        __half* p = g_attnh + ((size_t)bz*SEQ + s)*ASTRIDE + t;
        if (t + 3 < SEQ) {
            __half2 h0 = __floats2half2_rn(v.x, v.y);
            __half2 h1 = __floats2half2_rn(v.z, v.w);
            uint2 pk = make_uint2(*(uint32_t*)&h0, *(uint32_t*)&h1);
            *(uint2*)p = pk;
        } else {
            float vv[4] = {v.x, v.y, v.z, v.w};
#pragma unroll
            for (int e = 0; e < 4; e++) {
                int tt = t + e;
                if (tt < ASTRIDE) p[e] = __float2half((tt < SEQ) ? vv[e] : 0.f);
            }
        }
    }
}

// ---------------- softmax: warp-per-row, half in -> half out ----------------
__global__ void __launch_bounds__(256)
k_softmax_attn2() {
    int gw = blockIdx.x * 8 + (threadIdx.x >> 5);
    if (gw >= BATCH*NHEAD*SEQ) return;
    __half* p = g_attnh + (size_t)gw * ASTRIDE;
    int lane = threadIdx.x & 31;
    float v[7];
    float mx = -1e30f;
#pragma unroll
    for (int i = 0; i < 7; i++) {
        int t = lane + i*32;
        v[i] = (t < SEQ) ? __half2float(p[t]) : -1e30f;
        mx = fmaxf(mx, v[i]);
    }
#pragma unroll
    for (int o = 16; o > 0; o >>= 1) mx = fmaxf(mx, __shfl_xor_sync(0xffffffffu, mx, o));
    float sm = 0.f;
#pragma unroll
    for (int i = 0; i < 7; i++) {
        v[i] = (lane + i*32 < SEQ) ? expf(v[i] - mx) : 0.f;
        sm += v[i];
    }
#pragma unroll
    for (int o = 16; o > 0; o >>= 1) sm += __shfl_xor_sync(0xffffffffu, sm, o);
    float inv = 1.f / sm;
#pragma unroll
    for (int i = 0; i < 7; i++) {
        int t = lane + i*32;
        if (t < SEQ) p[t] = __float2half(v[i] * inv);
    }
}

// ---------------- o = attn @ v (tf32 compute, half probs in) ---------------
__global__ void __launch_bounds__(128)
k_av_tc() {
    __shared__ float Ps[64][20];
    __shared__ float Vs[16][68];
    __shared__ float Epi[64][68];
    const int bz = blockIdx.y;
    const int b = bz / NHEAD, h = bz % NHEAD;
    const int s0 = blockIdx.x * 64;
    const int tid = threadIdx.x, wid = tid >> 5;
    const __half* Pb = g_attnh + (size_t)bz*SEQ*ASTRIDE;
    const float* V = g_v + (size_t)b*SEQ*DIM + h*DHEAD;

    wmma::fragment<wmma::accumulator, 16, 16, 8, float> acc[4];
#pragma unroll
    for (int j = 0; j < 4; j++) wmma::fill_fragment(acc[j], 0.f);

    for (int kc = 0; kc < 13; kc++) {
#pragma unroll
        for (int i = 0; i < 2; i++) {
            int ll = i * 128 + tid;
            int rr = ll >> 2, cc = ll & 3;
            int s = s0 + rr;
            float4 pv = make_float4(0.f,0.f,0.f,0.f);
            if (s < SEQ) {
                uint2 raw = *(const uint2*)(Pb + (size_t)s*ASTRIDE + kc*16 + cc*4);
                __half2 h0 = *(__half2*)&raw.x;
                __half2 h1 = *(__half2*)&raw.y;
                float2 f0 = __half22float2(h0);
                float2 f1 = __half22float2(h1);
                pv = make_float4(f0.x, f0.y, f1.x, f1.y);
            }
            *(float4*)&Ps[rr][cc*4] = pv;
            int l2 = i * 128 + tid;
            int vr = l2 >> 4, vc = l2 & 15;
            int t = kc*16 + vr;
            float4 vv = make_float4(0.f,0.f,0.f,0.f);
            if (t < SEQ) vv = *(const float4*)(V + (size_t)t*DIM + vc*4);
            *(float4*)&Vs[vr][vc*4] = vv;
        }
        __syncthreads();
#pragma unroll
        for (int ks = 0; ks < 2; ks++) {
            wmma::fragment<wmma::matrix_a, 16, 16, 8, wmma::precision::tf32, wmma::row_major> af;
            wmma::load_matrix_sync(af, &Ps[wid*16][ks*8], 20);
#pragma unroll
            for (int j = 0; j < 4; j++) {
                wmma::fragment<wmma::matrix_b, 16, 16, 8, wmma::precision::tf32, wmma::row_major> bf;
                wmma::load_matrix_sync(bf, &Vs[ks*8][j*16], 68);
                wmma::mma_sync(acc[j], af, bf, acc[j]);
            }
        }
        __syncthreads();
    }
#pragma unroll
    for (int j = 0; j < 4; j++)
        wmma::store_matrix_sync(&Epi[wid*16][j*16], acc[j], 68, wmma::mem_row_major);
    __syncthreads();
#pragma unroll
    for (int i = 0; i < 8; i++) {
        int ll = i * 128 + tid;
        int rr = ll >> 4, c4 = ll & 15;
        int s = s0 + rr;
        if (s >= SEQ) continue;
        float* tp = g_tokens + ((size_t)b*SEQ + s)*DIM + h*DHEAD + c4*4;
        float4 o = *(const float4*)tp;
        float4 v = *(float4*)&Epi[rr][c4*4];
        o.x += v.x; o.y += v.y; o.z += v.z; o.w += v.w;
        *(float4*)tp = o;
    }
}

// ---------------- transpose fp32 -> half [C,R] ------------------------------
__global__ void k_transpose_h(const float* __restrict__ in, __half* __restrict__ out,
                              int R, int C) {
    __shared__ float t[32][33];
    size_t lo = (size_t)blockIdx.z * R * C;
    int c0 = blockIdx.x * 32, r0 = blockIdx.y * 32;
#pragma unroll
    for (int i = 0; i < 4; i++) {
        int r = r0 + threadIdx.y + i * 8;
        int c = c0 + threadIdx.x;
        t[threadIdx.y + i * 8][threadIdx.x] = in[lo + (size_t)r * C + c];
    }
    __syncthreads();
#pragma unroll
    for (int i = 0; i < 4; i++) {
        int c = c0 + threadIdx.y + i * 8;
        int r = r0 + threadIdx.x;
        out[lo + (size_t)c * R + r] = __float2half(t[threadIdx.x][threadIdx.y + i * 8]);
    }
}

// ---------------- patchify (half out) ---------------------------------------
__global__ void k_patchify(const float* __restrict__ x, __half* __restrict__ out) {
    int idx = blockIdx.x * blockDim.x + threadIdx.x;
    const int total = MPAT * DIM;
    if (idx >= total) return;
    int e   = idx % DIM;
    int row = idx / DIM;
    int b  = row / NPATCH, p = row % NPATCH;
    int pi = p / 14, pj = p % 14;
    int c  = e / 256, r = e % 256;
    int ph = r / 16,  pw = r % 16;
    out[idx] = __float2half(x[(((b*3 + c)*224) + pi*16 + ph)*224 + pj*16 + pw]);
}

// ---------------- build tokens -----------------------------------------------
__global__ void k_build_tokens(const float* __restrict__ emb, const float* __restrict__ cls) {
    int idx = blockIdx.x * blockDim.x + threadIdx.x;
    if (idx >= MTOK * DIM) return;
    int d   = idx % DIM;
    int rem = idx / DIM;
    int s = rem % SEQ;
    int b = rem / SEQ;
    int jj = d & ~1;
    float p   = expf(-((float)jj / (float)DIM) * 9.210340371976184f);
    float arg = (float)s * p;
    float pe  = (d & 1) ? cosf(arg) : sinf(arg);
    float base = (s == 0) ? cls[d] : emb[(b*NPATCH + s - 1)*DIM + d];
    g_tokens[(size_t)b*SEQ*DIM + (size_t)s*DIM + d] = base + pe;
}

// ---------------- layernorm: writes fp32(r32) and/or half -------------------
__global__ void k_layernorm(const float* __restrict__ in, const float* __restrict__ gam,
                            const float* __restrict__ bet,
                            float* __restrict__ outf, __half* __restrict__ outh) {
    int row = blockIdx.x;
    int tid = threadIdx.x;
    const float* xr = in + (size_t)row * DIM;
    float xs[3];
    float s = 0.f;
#pragma unroll
    for (int i = 0; i < 3; i++) { xs[i] = xr[tid + i*256]; s += xs[i]; }
    __shared__ float red[8];
#pragma unroll
    for (int o = 16; o > 0; o >>= 1) s += __shfl_xor_sync(0xffffffffu, s, o);
    if ((tid & 31) == 0) red[tid >> 5] = s;
    __syncthreads();
    float mu = 0.f;
    {
        float tot = 0.f;
#pragma unroll
        for (int i = 0; i < 8; i++) tot += red[i];
        mu = tot * (1.f / DIM);
    }
    __syncthreads();
    float v = 0.f;
#pragma unroll
    for (int i = 0; i < 3; i++) { float dlt = xs[i] - mu; v += dlt * dlt; }
#pragma unroll
    for (int o = 16; o > 0; o >>= 1) v += __shfl_xor_sync(0xffffffffu, v, o);
    if ((tid & 31) == 0) red[tid >> 5] = v;
    __syncthreads();
    float var = 0.f;
#pragma unroll
    for (int i = 0; i < 8; i++) var += red[i];
    var *= (1.f / DIM);
    float rstd = rsqrtf(var + 1e-5f);
#pragma unroll
    for (int i = 0; i < 3; i++) {
        int d = tid + i*256;
        float y = (xs[i] - mu) * rstd * gam[d] + bet[d];
        if (outf) outf[(size_t)row*DIM + d] = r32(y);
        if (outh) outh[(size_t)row*DIM + d] = __float2half(y);
    }
}

// ---------------- SIMT SGEMM (tiny head GEMM) ------------------------------
template<int ACT, bool ACCUM>
__global__ void sgemm128(int M, int N, int K,
                         const float* __restrict__ A, int lda,
                         const float* __restrict__ Bm, int ldb,
                         const float* __restrict__ bias,
                         float* __restrict__ C, int ldc) {
    __shared__ float As[8][128];
    __shared__ float Bs[8][132];
    int tid = threadIdx.x;
    int tx = tid & 15, ty = tid >> 4;
    int row0 = blockIdx.y * 128, col0 = blockIdx.x * 128;
    float acc[8][8];
#pragma unroll
    for (int i = 0; i < 8; i++)
#pragma unroll
        for (int j = 0; j < 8; j++) acc[i][j] = 0.f;

    for (int kk = 0; kk < K; kk += 8) {
        {
            int idx = tid * 4;
            int r = idx >> 3, c = idx & 7;
            float4 v = make_float4(0.f, 0.f, 0.f, 0.f);
            int gr = row0 + r;
            if (gr < M) v = *(const float4*)(A + (size_t)gr * lda + kk + c);
            As[c+0][r] = v.x; As[c+1][r] = v.y; As[c+2][r] = v.z; As[c+3][r] = v.w;
        }
        {
            int idx = tid * 4;
            int r = idx >> 7, c = idx & 127;
            int gc = col0 + c;
            float4 v;
            if (gc + 3 < N) {
                v = *(const float4*)(Bm + (size_t)(kk + r) * ldb + gc);
            } else {
                float t0 = (gc+0 < N) ? Bm[(size_t)(kk+r)*ldb + gc+0] : 0.f;
                float t1 = (gc+1 < N) ? Bm[(size_t)(kk+r)*ldb + gc+1] : 0.f;
                float t2 = (gc+2 < N) ? Bm[(size_t)(kk+r)*ldb + gc+2] : 0.f;
                float t3 = (gc+3 < N) ? Bm[(size_t)(kk+r)*ldb + gc+3] : 0.f;
                v = make_float4(t0, t1, t2, t3);
            }
            *(float4*)&Bs[r][c] = v;
        }
        __syncthreads();
#pragma unroll
        for (int k = 0; k < 8; k++) {
            float a[8], b[8];
            *(float4*)&a[0] = *(const float4*)&As[k][ty*8];
            *(float4*)&a[4] = *(const float4*)&As[k][ty*8 + 4];
            *(float4*)&b[0] = *(const float4*)&Bs[k][tx*8];
            *(float4*)&b[4] = *(const float4*)&Bs[k][tx*8 + 4];
#pragma unroll
            for (int i = 0; i < 8; i++)
#pragma unroll
                for (int j = 0; j < 8; j++)
                    acc[i][j] = fmaf(a[i], b[j], acc[i][j]);
        }
        __syncthreads();
    }
#pragma unroll
    for (int i = 0; i < 8; i++) {
        int gr = row0 + ty*8 + i;
        if (gr >= M) continue;
#pragma unroll
        for (int j = 0; j < 8; j++) {
            int gc = col0 + tx*8 + j;
            if (gc >= N) continue;
            float v = acc[i][j] + (bias ? bias[gc] : 0.f);
            if (ACT == 1) v = gelu_exact(v);
            if (ACCUM) C[(size_t)gr*ldc + gc] += v;
            else       C[(size_t)gr*ldc + gc]  = v;
        }
    }
}

// ---------------- output softmax --------------------------------------------
__global__ void k_softmax_out(const float* __restrict__ logits, float* __restrict__ out) {
    int row = blockIdx.x;
    int tid = threadIdx.x;
    const float* p = logits + (size_t)row * NOUT;
    float v[4];
    float mx = -1e30f;
#pragma unroll
    for (int i = 0; i < 4; i++) {
        int idx = tid + i*256;
        v[i] = (idx < NOUT) ? p[idx] : -1e30f;
        mx = fmaxf(mx, v[i]);
    }
    __shared__ float red[8];
#pragma unroll
    for (int o = 16; o > 0; o >>= 1) mx = fmaxf(mx, __shfl_xor_sync(0xffffffffu, mx, o));
    if ((tid & 31) == 0) red[tid >> 5] = mx;
    __syncthreads();
    float m2 = red[0];
#pragma unroll
    for (int i = 1; i < 8; i++) m2 = fmaxf(m2, red[i]);
    float e[4], sm = 0.f;
#pragma unroll
    for (int i = 0; i < 4; i++) {
        int idx = tid + i*256;
        e[i] = (idx < NOUT) ? expf(v[i] - m2) : 0.f;
        sm += e[i];
    }
#pragma unroll
    for (int o = 16; o > 0; o >>= 1) sm += __shfl_xor_sync(0xffffffffu, sm, o);
    __syncthreads();
    if ((tid & 31) == 0) red[tid >> 5] = sm;
    __syncthreads();
    float tot = 0.f;
#pragma unroll
    for (int i = 0; i < 8; i++) tot += red[i];
    float inv = 1.f / tot;
#pragma unroll
    for (int i = 0; i < 4; i++) {
        int idx = tid + i*256;
        if (idx < NOUT) out[(size_t)row*NOUT + idx] = e[i] * inv;
    }
}

// ============================ host launcher =================================
extern "C" void kernel_launch(void* const* d_in, const int* in_sizes, int n_in,
                              void* d_out, int out_size) {
    (void)in_sizes; (void)n_in; (void)out_size;
    const float* x       = (const float*)d_in[0];
    const float* w_embed = (const float*)d_in[1];
    const float* b_embed = (const float*)d_in[2];
    const float* cls     = (const float*)d_in[3];
    const float* ln1_g   = (const float*)d_in[4];
    const float* ln1_b   = (const float*)d_in[5];
    const float* wq      = (const float*)d_in[6];
    const float* bq      = (const float*)d_in[7];
    const float* wk      = (const float*)d_in[8];
    const float* bk      = (const float*)d_in[9];
    const float* wv      = (const float*)d_in[10];
    const float* bv      = (const float*)d_in[11];
    const float* ln2_g   = (const float*)d_in[12];
    const float* ln2_b   = (const float*)d_in[13];
    const float* w1      = (const float*)d_in[14];
    const float* b1      = (const float*)d_in[15];
    const float* w2      = (const float*)d_in[16];
    const float* b2      = (const float*)d_in[17];
    const float* w_head  = (const float*)d_in[18];
    const float* b_head  = (const float*)d_in[19];
    float* out = (float*)d_out;

    float *p_tokens, *p_embf, *p_h;
    __half *p_hh, *p_mlph, *p_ph, *p_w1t, *p_w2t, *p_wembt;
    cudaGetSymbolAddress((void**)&p_tokens, g_tokens);
    cudaGetSymbolAddress((void**)&p_embf,   g_embf);
    cudaGetSymbolAddress((void**)&p_h,      g_h);
    cudaGetSymbolAddress((void**)&p_hh,     g_hh);
    cudaGetSymbolAddress((void**)&p_mlph,   g_mlph);
    cudaGetSymbolAddress((void**)&p_ph,     g_ph);
    cudaGetSymbolAddress((void**)&p_w1t,    g_w1t);
    cudaGetSymbolAddress((void**)&p_w2t,    g_w2t);
    cudaGetSymbolAddress((void**)&p_wembt,  g_wembt);

    cudaFuncSetAttribute(gemm_h<0,0>, cudaFuncAttributeMaxDynamicSharedMemorySize, GH_SMEM_BYTES);
    cudaFuncSetAttribute(gemm_h<1,2>, cudaFuncAttributeMaxDynamicSharedMemorySize, GH_SMEM_BYTES);
    cudaFuncSetAttribute(gemm_h<0,1>, cudaFuncAttributeMaxDynamicSharedMemorySize, GH_SMEM_BYTES);

    // ---- startup ----
    dim3 tb(32, 8);
    k_patchify<<<(MPAT*DIM + 255)/256, 256>>>(x, p_ph);
    k_transpose_h<<<dim3(DIM/32, DIM/32, 1), tb>>>(w_embed, p_wembt, DIM, DIM);
    k_transpose_h<<<dim3(MLPD/32, DIM/32, NLAYER), tb>>>(w1, p_w1t, DIM, MLPD);
    gemm_h<0,0><<<dim3(DIM/128, (MPAT+127)/128), 256, GH_SMEM_BYTES>>>(
        MPAT, DIM, p_ph, DIM, p_wembt, DIM, b_embed, p_embf, nullptr, DIM);
    k_transpose_h<<<dim3(DIM/32, MLPD/32, NLAYER), tb>>>(w2, p_w2t, MLPD, DIM);
    k_build_tokens<<<(MTOK*DIM + 255)/256, 256>>>(p_embf, cls);

    // ---- transformer layers ----
    const int softmax_rows = BATCH*NHEAD*SEQ;
    for (int l = 0; l < NLAYER; l++) {
        k_layernorm<<<MTOK, 256>>>(p_tokens, ln1_g + l*DIM, ln1_b + l*DIM, p_h, nullptr);
        k_qkv_tc<<<dim3((MTOK + 63)/64, NHEAD, 3), 128>>>(wq, wk, wv, bq, bk, bv, l);
        k_scores_tc<<<dim3(4, 4, BATCH*NHEAD), 128>>>();
        k_softmax_attn2<<<(softmax_rows + 7)/8, 256>>>();
        k_av_tc<<<dim3(4, BATCH*NHEAD), 128>>>();
        k_layernorm<<<MTOK, 256>>>(p_tokens, ln2_g + l*DIM, ln2_b + l*DIM, nullptr, p_hh);
        gemm_h<1,2><<<dim3(MLPD/128, (MTOK+127)/128), 256, GH_SMEM_BYTES>>>(
            MTOK, DIM, p_hh, DIM, p_w1t + (size_t)l*MLPD*DIM, DIM,
            b1 + (size_t)l*MLPD, nullptr, p_mlph, MLPD);
        gemm_h<0,1><<<dim3(DIM/128, (MTOK+127)/128), 256, GH_SMEM_BYTES>>>(
            MTOK, MLPD, p_mlph, MLPD, p_w2t + (size_t)l*DIM*MLPD, MLPD,
            b2 + (size_t)l*DIM, p_tokens, nullptr, DIM);
    }

    // ---- classification head + softmax ----
    sgemm128<0, false><<<dim3(8, 1), 256>>>(BATCH, NOUT, DIM, p_tokens, SEQ*DIM,
                                            w_head, NOUT, b_head, p_embf, NOUT);
    k_softmax_out<<<BATCH, 256>>>(p_embf, out);
}

// round 14
// speedup vs baseline: 1.5039x; 1.5039x over previous
#include <cuda_runtime.h>
#include <cuda_fp16.h>
#include <math.h>
#include <stdint.h>
#include <mma.h>

using namespace nvcuda;

#define BATCH 32
#define SEQ 197
#define DIM 768
#define NHEAD 12
#define DHEAD 64
#define NLAYER 12
#define MLPD 3072
#define NOUT 1000
#define NPATCH 196
#define MTOK (BATCH*SEQ)        /* 6304 */
#define MPAT (BATCH*NPATCH)     /* 6272 */
#define ASTRIDE 208             /* padded attn row stride */

// ---------------- scratch (device globals) ----------------------------------
__device__ float  g_tokens[MTOK*DIM];
__device__ float  g_embf[MPAT*DIM];
__device__ float  g_h[MTOK*DIM];
__device__ float  g_q[MTOK*DIM];
__device__ float  g_k[MTOK*DIM];
__device__ float  g_v[MTOK*DIM];
__device__ float  g_attn[(size_t)BATCH*NHEAD*SEQ*ASTRIDE];
__device__ __half g_hh[MTOK*DIM];
__device__ __half g_mlph[(size_t)MTOK*MLPD];
__device__ __half g_ph[(size_t)MPAT*DIM];
__device__ __half g_w1t[(size_t)NLAYER*MLPD*DIM];   // [l][N=3072][K=768]
__device__ __half g_w2t[(size_t)NLAYER*DIM*MLPD];   // [l][N=768][K=3072]
__device__ __half g_wembt[DIM*DIM];                 // [N=768][K=768]

__device__ __forceinline__ float gelu_exact(float x) {
    return 0.5f * x * (1.f + erff(x * 0.70710678118654752f));
}
__device__ __forceinline__ float r32(float x) { return wmma::__float_to_tf32(x); }
__device__ __forceinline__ uint32_t s2u(const void* p) {
    uint32_t a;
    asm("{ .reg .u64 t; cvta.to.shared.u64 t, %1; cvt.u32.u64 %0, t; }" : "=r"(a) : "l"(p));
    return a;
}
__device__ __forceinline__ void cp16(uint32_t dst, const void* src, bool pred) {
    int sz = pred ? 16 : 0;
    asm volatile("cp.async.ca.shared.global [%0], [%1], 16, %2;"
                 :: "r"(dst), "l"(src), "r"(sz));
}
#define CP_COMMIT() asm volatile("cp.async.commit_group;" ::: "memory")
#define CP_WAIT0()  asm volatile("cp.async.wait_group 0;" ::: "memory")

// ================= fp16 wmma GEMM: 256 thr, 8 warps (2x4), warp 64x32 =======
#define GH_LDS 72
#define GH_BUF (128*GH_LDS)
#define GH_LDE 132
#define GH_SMEM_BYTES (4*GH_BUF*2 > 128*GH_LDE*4 ? 4*GH_BUF*2 : 128*GH_LDE*4)

template<int ACT, int OUTMODE>
__global__ void __launch_bounds__(256, 2)
gemm_h(int M, int K,
       const __half* __restrict__ A, int lda,
       const __half* __restrict__ Bt, int ldb,
       const float* __restrict__ bias,
       float* __restrict__ Cf, __half* __restrict__ Ch, int ldc) {
    extern __shared__ __align__(128) __half smh[];
    const int tid = threadIdx.x;
    const int wid = tid >> 5;
    const int row0 = blockIdx.y * 128, col0 = blockIdx.x * 128;
    const int wm = wid & 1, wn = wid >> 1;

    wmma::fragment<wmma::accumulator, 16, 16, 16, float> acc[4][2];
#pragma unroll
    for (int i = 0; i < 4; i++)
#pragma unroll
        for (int j = 0; j < 2; j++) wmma::fill_fragment(acc[i][j], 0.f);

    const int nc = K >> 6;
    const int r = tid >> 3, c = tid & 7;

    {   // stage 0
        __half* As = smh;
        __half* Bs = smh + 2*GH_BUF;
#pragma unroll
        for (int i = 0; i < 4; i++) {
            int rr = r + i * 32;
            cp16(s2u(&As[rr * GH_LDS + c * 8]),
                 A + (size_t)(row0 + rr) * lda + c * 8, (row0 + rr) < M);
            cp16(s2u(&Bs[rr * GH_LDS + c * 8]),
                 Bt + (size_t)(col0 + rr) * ldb + c * 8, true);
        }
        CP_COMMIT();
    }

    for (int kc = 0; kc < nc; kc++) {
        const int cur = kc & 1;
        CP_WAIT0();
        __syncthreads();
        if (kc + 1 < nc) {
            const int nxt = 1 - cur;
            const int ko = (kc + 1) * 64;
            __half* As = smh + nxt * GH_BUF;
            __half* Bs = smh + 2*GH_BUF + nxt * GH_BUF;
#pragma unroll
            for (int i = 0; i < 4; i++) {
                int rr = r + i * 32;
                cp16(s2u(&As[rr * GH_LDS + c * 8]),
                     A + (size_t)(row0 + rr) * lda + ko + c * 8, (row0 + rr) < M);
                cp16(s2u(&Bs[rr * GH_LDS + c * 8]),
                     Bt + (size_t)(col0 + rr) * ldb + ko + c * 8, true);
            }
            CP_COMMIT();
        }
        const __half* As = smh + cur * GH_BUF;
        const __half* Bs = smh + 2*GH_BUF + cur * GH_BUF;
#pragma unroll
        for (int ks = 0; ks < 4; ks++) {
            wmma::fragment<wmma::matrix_a, 16, 16, 16, __half, wmma::row_major> af[4];
#pragma unroll
            for (int i = 0; i < 4; i++)
                wmma::load_matrix_sync(af[i], &As[(wm*64 + i*16) * GH_LDS + ks*16], GH_LDS);
#pragma unroll
            for (int j = 0; j < 2; j++) {
                wmma::fragment<wmma::matrix_b, 16, 16, 16, __half, wmma::col_major> bf;
                wmma::load_matrix_sync(bf, &Bs[(wn*32 + j*16) * GH_LDS + ks*16], GH_LDS);
#pragma unroll
                for (int i = 0; i < 4; i++)
                    wmma::mma_sync(acc[i][j], af[i], bf, acc[i][j]);
            }
        }
    }

    __syncthreads();
    float* Epi = (float*)smh;
#pragma unroll
    for (int i = 0; i < 4; i++)
#pragma unroll
        for (int j = 0; j < 2; j++)
            wmma::store_matrix_sync(&Epi[(wm*64 + i*16) * GH_LDE + wn*32 + j*16],
                                    acc[i][j], GH_LDE, wmma::mem_row_major);
    __syncthreads();
#pragma unroll 4
    for (int it = 0; it < 16; it++) {
        int l = it * 256 + tid;
        int rr = l >> 5, c4 = l & 31;
        int gr = row0 + rr;
        if (gr >= M) continue;
        float4 v = *(float4*)&Epi[rr * GH_LDE + c4 * 4];
        int gc = col0 + c4 * 4;
        v.x += bias[gc+0]; v.y += bias[gc+1]; v.z += bias[gc+2]; v.w += bias[gc+3];
        if (ACT == 1) {
            v.x = gelu_exact(v.x); v.y = gelu_exact(v.y);
            v.z = gelu_exact(v.z); v.w = gelu_exact(v.w);
        }
        if (OUTMODE == 2) {
            __half2 h0 = __floats2half2_rn(v.x, v.y);
            __half2 h1 = __floats2half2_rn(v.z, v.w);
            uint2 pk = make_uint2(*(uint32_t*)&h0, *(uint32_t*)&h1);
            *(uint2*)(Ch + (size_t)gr * ldc + gc) = pk;
        } else {
            float* cp = Cf + (size_t)gr * ldc + gc;
            if (OUTMODE == 1) {
                float4 o = *(const float4*)cp;
                v.x += o.x; v.y += o.y; v.z += o.z; v.w += o.w;
            }
            *(float4*)cp = v;
        }
    }
}

// ---------------- QKV projection (wmma tf32, verified) ----------------------
__global__ void __launch_bounds__(128)
k_qkv_tc(const float* __restrict__ wq, const float* __restrict__ wk,
         const float* __restrict__ wv, const float* __restrict__ bq,
         const float* __restrict__ bk, const float* __restrict__ bv, int l) {
    __shared__ float Hs[64][68];
    __shared__ float Ws[64][68];
    __shared__ float Epi[64][68];
    int head = blockIdx.y, which = blockIdx.z;
    const float* W; const float* bias; float* out;
    if (which == 0)      { W = wq; bias = bq; out = g_q; }
    else if (which == 1) { W = wk; bias = bk; out = g_k; }
    else                 { W = wv; bias = bv; out = g_v; }
    W    += ((size_t)l*NHEAD + head) * DHEAD * DHEAD;
    bias += ((size_t)l*NHEAD + head) * DHEAD;
    const int m0 = blockIdx.x * 64;
    const int tid = threadIdx.x, wid = tid >> 5;

#pragma unroll
    for (int i = 0; i < 8; i++) {
        int ll = i * 128 + tid;
        int rr = ll >> 4, c4 = ll & 15;
        float4 v = make_float4(0.f,0.f,0.f,0.f);
        if (m0 + rr < MTOK)
            v = *(const float4*)(g_h + (size_t)(m0 + rr)*DIM + head*DHEAD + c4*4);
        *(float4*)&Hs[rr][c4*4] = v;
        float4 w = *(const float4*)(W + rr*64 + c4*4);
        w.x = r32(w.x); w.y = r32(w.y); w.z = r32(w.z); w.w = r32(w.w);
        *(float4*)&Ws[rr][c4*4] = w;
    }
    __syncthreads();

    wmma::fragment<wmma::accumulator, 16, 16, 8, float> acc[4];
#pragma unroll
    for (int j = 0; j < 4; j++) wmma::fill_fragment(acc[j], 0.f);
#pragma unroll
    for (int ks = 0; ks < 8; ks++) {
        wmma::fragment<wmma::matrix_a, 16, 16, 8, wmma::precision::tf32, wmma::row_major> af;
        wmma::load_matrix_sync(af, &Hs[wid*16][ks*8], 68);
#pragma unroll
        for (int j = 0; j < 4; j++) {
            wmma::fragment<wmma::matrix_b, 16, 16, 8, wmma::precision::tf32, wmma::row_major> bf;
            wmma::load_matrix_sync(bf, &Ws[ks*8][j*16], 68);
            wmma::mma_sync(acc[j], af, bf, acc[j]);
        }
    }
#pragma unroll
    for (int j = 0; j < 4; j++)
        wmma::store_matrix_sync(&Epi[wid*16][j*16], acc[j], 68, wmma::mem_row_major);
    __syncthreads();
#pragma unroll
    for (int i = 0; i < 8; i++) {
        int ll = i * 128 + tid;
        int rr = ll >> 4, c4 = ll & 15;
        int gr = m0 + rr;
        if (gr >= MTOK) continue;
        float4 v = *(float4*)&Epi[rr][c4*4];
        v.x = r32(v.x + bias[c4*4+0]); v.y = r32(v.y + bias[c4*4+1]);
        v.z = r32(v.z + bias[c4*4+2]); v.w = r32(v.w + bias[c4*4+3]);
        *(float4*)(out + (size_t)gr*DIM + head*DHEAD + c4*4) = v;
    }
}

// ---------------- attention scores (wmma tf32, verified) --------------------
__global__ void __launch_bounds__(128)
k_scores_tc() {
    __shared__ float Qs[64][68];
    __shared__ float Ks[64][68];
    __shared__ float Epi[64][68];
    const int bz = blockIdx.z;
    const int b = bz / NHEAD, h = bz % NHEAD;
    const int t0 = blockIdx.x * 64, s0 = blockIdx.y * 64;
    const int tid = threadIdx.x, wid = tid >> 5;
    const float* Q = g_q + (size_t)b*SEQ*DIM + h*DHEAD;
    const float* K = g_k + (size_t)b*SEQ*DIM + h*DHEAD;

#pragma unroll
    for (int i = 0; i < 8; i++) {
        int ll = i * 128 + tid;
        int rr = ll >> 4, c4 = ll & 15;
        float4 q = make_float4(0.f,0.f,0.f,0.f);
        if (s0 + rr < SEQ) q = *(const float4*)(Q + (size_t)(s0 + rr)*DIM + c4*4);
        *(float4*)&Qs[rr][c4*4] = q;
        float4 k = make_float4(0.f,0.f,0.f,0.f);
        if (t0 + rr < SEQ) k = *(const float4*)(K + (size_t)(t0 + rr)*DIM + c4*4);
        *(float4*)&Ks[rr][c4*4] = k;
    }
    __syncthreads();

    wmma::fragment<wmma::accumulator, 16, 16, 8, float> acc[4];
#pragma unroll
    for (int j = 0; j < 4; j++) wmma::fill_fragment(acc[j], 0.f);
#pragma unroll
    for (int ks = 0; ks < 8; ks++) {
        wmma::fragment<wmma::matrix_a, 16, 16, 8, wmma::precision::tf32, wmma::row_major> af;
        wmma::load_matrix_sync(af, &Qs[wid*16][ks*8], 68);
#pragma unroll
        for (int j = 0; j < 4; j++) {
            wmma::fragment<wmma::matrix_b, 16, 16, 8, wmma::precision::tf32, wmma::col_major> bf;
            wmma::load_matrix_sync(bf, &Ks[j*16][ks*8], 68);
            wmma::mma_sync(acc[j], af, bf, acc[j]);
        }
    }
#pragma unroll
    for (int j = 0; j < 4; j++)
        wmma::store_matrix_sync(&Epi[wid*16][j*16], acc[j], 68, wmma::mem_row_major);
    __syncthreads();
#pragma unroll
    for (int i = 0; i < 8; i++) {
        int ll = i * 128 + tid;
        int rr = ll >> 4, c4 = ll & 15;
        int s = s0 + rr;
        if (s >= SEQ) continue;
        int t = t0 + c4*4;
        if (t >= ASTRIDE) continue;
        float4 v = *(float4*)&Epi[rr][c4*4];
        v.x *= 0.125f; v.y *= 0.125f; v.z *= 0.125f; v.w *= 0.125f;
        float* p = g_attn + ((size_t)bz*SEQ + s)*ASTRIDE + t;
        if (t + 3 < SEQ) {
            *(float4*)p = v;
        } else {
            float vv[4] = {v.x, v.y, v.z, v.w};
#pragma unroll
            for (int e = 0; e < 4; e++) {
                int tt = t + e;
                if (tt < ASTRIDE) p[e] = (tt < SEQ) ? vv[e] : 0.f;
            }
        }
    }
}

// ---------------- softmax: warp-per-row, 8 rows/block (verified) -----------
__global__ void __launch_bounds__(256)
k_softmax_attn2() {
    int gw = blockIdx.x * 8 + (threadIdx.x >> 5);
    if (gw >= BATCH*NHEAD*SEQ) return;
    float* p = g_attn + (size_t)gw * ASTRIDE;
    int lane = threadIdx.x & 31;
    float v[7];
    float mx = -1e30f;
#pragma unroll
    for (int i = 0; i < 7; i++) {
        int t = lane + i*32;
        v[i] = (t < SEQ) ? p[t] : -1e30f;
        mx = fmaxf(mx, v[i]);
    }
#pragma unroll
    for (int o = 16; o > 0; o >>= 1) mx = fmaxf(mx, __shfl_xor_sync(0xffffffffu, mx, o));
    float sm = 0.f;
#pragma unroll
    for (int i = 0; i < 7; i++) {
        v[i] = (lane + i*32 < SEQ) ? expf(v[i] - mx) : 0.f;
        sm += v[i];
    }
#pragma unroll
    for (int o = 16; o > 0; o >>= 1) sm += __shfl_xor_sync(0xffffffffu, sm, o);
    float inv = 1.f / sm;
#pragma unroll
    for (int i = 0; i < 7; i++) {
        int t = lane + i*32;
        if (t < SEQ) p[t] = r32(v[i] * inv);
    }
}

// ---------------- o = attn @ v (wmma tf32, verified), fused residual -------
__global__ void __launch_bounds__(128)
k_av_tc() {
    __shared__ float Ps[64][20];
    __shared__ float Vs[16][68];
    __shared__ float Epi[64][68];
    const int bz = blockIdx.y;
    const int b = bz / NHEAD, h = bz % NHEAD;
    const int s0 = blockIdx.x * 64;
    const int tid = threadIdx.x, wid = tid >> 5;
    const float* Pb = g_attn + (size_t)bz*SEQ*ASTRIDE;
    const float* V = g_v + (size_t)b*SEQ*DIM + h*DHEAD;

    wmma::fragment<wmma::accumulator, 16, 16, 8, float> acc[4];
#pragma unroll
    for (int j = 0; j < 4; j++) wmma::fill_fragment(acc[j], 0.f);

    for (int kc = 0; kc < 13; kc++) {
#pragma unroll
        for (int i = 0; i < 2; i++) {
            int ll = i * 128 + tid;
            int rr = ll >> 2, cc = ll & 3;
            int s = s0 + rr;
            float4 pv = make_float4(0.f,0.f,0.f,0.f);
            if (s < SEQ) pv = *(const float4*)(Pb + (size_t)s*ASTRIDE + kc*16 + cc*4);
            *(float4*)&Ps[rr][cc*4] = pv;
            int l2 = i * 128 + tid;
            int vr = l2 >> 4, vc = l2 & 15;
            int t = kc*16 + vr;
            float4 vv = make_float4(0.f,0.f,0.f,0.f);
            if (t < SEQ) vv = *(const float4*)(V + (size_t)t*DIM + vc*4);
            *(float4*)&Vs[vr][vc*4] = vv;
        }
        __syncthreads();
#pragma unroll
        for (int ks = 0; ks < 2; ks++) {
            wmma::fragment<wmma::matrix_a, 16, 16, 8, wmma::precision::tf32, wmma::row_major> af;
            wmma::load_matrix_sync(af, &Ps[wid*16][ks*8], 20);
#pragma unroll
            for (int j = 0; j < 4; j++) {
                wmma::fragment<wmma::matrix_b, 16, 16, 8, wmma::precision::tf32, wmma::row_major> bf;
                wmma::load_matrix_sync(bf, &Vs[ks*8][j*16], 68);
                wmma::mma_sync(acc[j], af, bf, acc[j]);
            }
        }
        __syncthreads();
    }
#pragma unroll
    for (int j = 0; j < 4; j++)
        wmma::store_matrix_sync(&Epi[wid*16][j*16], acc[j], 68, wmma::mem_row_major);
    __syncthreads();
#pragma unroll
    for (int i = 0; i < 8; i++) {
        int ll = i * 128 + tid;
        int rr = ll >> 4, c4 = ll & 15;
        int s = s0 + rr;
        if (s >= SEQ) continue;
        float* tp = g_tokens + ((size_t)b*SEQ + s)*DIM + h*DHEAD + c4*4;
        float4 o = *(const float4*)tp;
        float4 v = *(float4*)&Epi[rr][c4*4];
        o.x += v.x; o.y += v.y; o.z += v.z; o.w += v.w;
        *(float4*)tp = o;
    }
}

// ---------------- transpose fp32 -> half [C,R] ------------------------------
__global__ void k_transpose_h(const float* __restrict__ in, __half* __restrict__ out,
                              int R, int C) {
    __shared__ float t[32][33];
    size_t lo = (size_t)blockIdx.z * R * C;
    int c0 = blockIdx.x * 32, r0 = blockIdx.y * 32;
#pragma unroll
    for (int i = 0; i < 4; i++) {
        int r = r0 + threadIdx.y + i * 8;
        int c = c0 + threadIdx.x;
        t[threadIdx.y + i * 8][threadIdx.x] = in[lo + (size_t)r * C + c];
    }
    __syncthreads();
#pragma unroll
    for (int i = 0; i < 4; i++) {
        int c = c0 + threadIdx.y + i * 8;
        int r = r0 + threadIdx.x;
        out[lo + (size_t)c * R + r] = __float2half(t[threadIdx.x][threadIdx.y + i * 8]);
    }
}

// ---------------- patchify (half out) ---------------------------------------
__global__ void k_patchify(const float* __restrict__ x, __half* __restrict__ out) {
    int idx = blockIdx.x * blockDim.x + threadIdx.x;
    const int total = MPAT * DIM;
    if (idx >= total) return;
    int e   = idx % DIM;
    int row = idx / DIM;
    int b  = row / NPATCH, p = row % NPATCH;
    int pi = p / 14, pj = p % 14;
    int c  = e / 256, r = e % 256;
    int ph = r / 16,  pw = r % 16;
    out[idx] = __float2half(x[(((b*3 + c)*224) + pi*16 + ph)*224 + pj*16 + pw]);
}

// ---------------- build tokens -----------------------------------------------
__global__ void k_build_tokens(const float* __restrict__ emb, const float* __restrict__ cls) {
    int idx = blockIdx.x * blockDim.x + threadIdx.x;
    if (idx >= MTOK * DIM) return;
    int d   = idx % DIM;
    int rem = idx / DIM;
    int s = rem % SEQ;
    int b = rem / SEQ;
    int jj = d & ~1;
    float p   = expf(-((float)jj / (float)DIM) * 9.210340371976184f);
    float arg = (float)s * p;
    float pe  = (d & 1) ? cosf(arg) : sinf(arg);
    float base = (s == 0) ? cls[d] : emb[(b*NPATCH + s - 1)*DIM + d];
    g_tokens[(size_t)b*SEQ*DIM + (size_t)s*DIM + d] = base + pe;
}

// ---------------- layernorm: writes fp32(r32) and/or half -------------------
__global__ void k_layernorm(const float* __restrict__ in, const float* __restrict__ gam,
                            const float* __restrict__ bet,
                            float* __restrict__ outf, __half* __restrict__ outh) {
    int row = blockIdx.x;
    int tid = threadIdx.x;
    const float* xr = in + (size_t)row * DIM;
    float xs[3];
    float s = 0.f;
#pragma unroll
    for (int i = 0; i < 3; i++) { xs[i] = xr[tid + i*256]; s += xs[i]; }
    __shared__ float red[8];
#pragma unroll
    for (int o = 16; o > 0; o >>= 1) s += __shfl_xor_sync(0xffffffffu, s, o);
    if ((tid & 31) == 0) red[tid >> 5] = s;
    __syncthreads();
    float mu = 0.f;
    {
        float tot = 0.f;
#pragma unroll
        for (int i = 0; i < 8; i++) tot += red[i];
        mu = tot * (1.f / DIM);
    }
    __syncthreads();
    float v = 0.f;
#pragma unroll
    for (int i = 0; i < 3; i++) { float dlt = xs[i] - mu; v += dlt * dlt; }
#pragma unroll
    for (int o = 16; o > 0; o >>= 1) v += __shfl_xor_sync(0xffffffffu, v, o);
    if ((tid & 31) == 0) red[tid >> 5] = v;
    __syncthreads();
    float var = 0.f;
#pragma unroll
    for (int i = 0; i < 8; i++) var += red[i];
    var *= (1.f / DIM);
    float rstd = rsqrtf(var + 1e-5f);
#pragma unroll
    for (int i = 0; i < 3; i++) {
        int d = tid + i*256;
        float y = (xs[i] - mu) * rstd * gam[d] + bet[d];
        if (outf) outf[(size_t)row*DIM + d] = r32(y);
        if (outh) outh[(size_t)row*DIM + d] = __float2half(y);
    }
}

// ---------------- SIMT SGEMM (tiny head GEMM) ------------------------------
template<int ACT, bool ACCUM>
__global__ void sgemm128(int M, int N, int K,
                         const float* __restrict__ A, int lda,
                         const float* __restrict__ Bm, int ldb,
                         const float* __restrict__ bias,
                         float* __restrict__ C, int ldc) {
    __shared__ float As[8][128];
    __shared__ float Bs[8][132];
    int tid = threadIdx.x;
    int tx = tid & 15, ty = tid >> 4;
    int row0 = blockIdx.y * 128, col0 = blockIdx.x * 128;
    float acc[8][8];
#pragma unroll
    for (int i = 0; i < 8; i++)
#pragma unroll
        for (int j = 0; j < 8; j++) acc[i][j] = 0.f;

    for (int kk = 0; kk < K; kk += 8) {
        {
            int idx = tid * 4;
            int r = idx >> 3, c = idx & 7;
            float4 v = make_float4(0.f, 0.f, 0.f, 0.f);
            int gr = row0 + r;
            if (gr < M) v = *(const float4*)(A + (size_t)gr * lda + kk + c);
            As[c+0][r] = v.x; As[c+1][r] = v.y; As[c+2][r] = v.z; As[c+3][r] = v.w;
        }
        {
            int idx = tid * 4;
            int r = idx >> 7, c = idx & 127;
            int gc = col0 + c;
            float4 v;
            if (gc + 3 < N) {
                v = *(const float4*)(Bm + (size_t)(kk + r) * ldb + gc);
            } else {
                float t0 = (gc+0 < N) ? Bm[(size_t)(kk+r)*ldb + gc+0] : 0.f;
                float t1 = (gc+1 < N) ? Bm[(size_t)(kk+r)*ldb + gc+1] : 0.f;
                float t2 = (gc+2 < N) ? Bm[(size_t)(kk+r)*ldb + gc+2] : 0.f;
                float t3 = (gc+3 < N) ? Bm[(size_t)(kk+r)*ldb + gc+3] : 0.f;
                v = make_float4(t0, t1, t2, t3);
            }
            *(float4*)&Bs[r][c] = v;
        }
        __syncthreads();
#pragma unroll
        for (int k = 0; k < 8; k++) {
            float a[8], b[8];
            *(float4*)&a[0] = *(const float4*)&As[k][ty*8];
            *(float4*)&a[4] = *(const float4*)&As[k][ty*8 + 4];
            *(float4*)&b[0] = *(const float4*)&Bs[k][tx*8];
            *(float4*)&b[4] = *(const float4*)&Bs[k][tx*8 + 4];
#pragma unroll
            for (int i = 0; i < 8; i++)
#pragma unroll
                for (int j = 0; j < 8; j++)
                    acc[i][j] = fmaf(a[i], b[j], acc[i][j]);
        }
        __syncthreads();
    }
#pragma unroll
    for (int i = 0; i < 8; i++) {
        int gr = row0 + ty*8 + i;
        if (gr >= M) continue;
#pragma unroll
        for (int j = 0; j < 8; j++) {
            int gc = col0 + tx*8 + j;
            if (gc >= N) continue;
            float v = acc[i][j] + (bias ? bias[gc] : 0.f);
            if (ACT == 1) v = gelu_exact(v);
            if (ACCUM) C[(size_t)gr*ldc + gc] += v;
            else       C[(size_t)gr*ldc + gc]  = v;
        }
    }
}

// ---------------- output softmax --------------------------------------------
__global__ void k_softmax_out(const float* __restrict__ logits, float* __restrict__ out) {
    int row = blockIdx.x;
    int tid = threadIdx.x;
    const float* p = logits + (size_t)row * NOUT;
    float v[4];
    float mx = -1e30f;
#pragma unroll
    for (int i = 0; i < 4; i++) {
        int idx = tid + i*256;
        v[i] = (idx < NOUT) ? p[idx] : -1e30f;
        mx = fmaxf(mx, v[i]);
    }
    __shared__ float red[8];
#pragma unroll
    for (int o = 16; o > 0; o >>= 1) mx = fmaxf(mx, __shfl_xor_sync(0xffffffffu, mx, o));
    if ((tid & 31) == 0) red[tid >> 5] = mx;
    __syncthreads();
    float m2 = red[0];
#pragma unroll
    for (int i = 1; i < 8; i++) m2 = fmaxf(m2, red[i]);
    float e[4], sm = 0.f;
#pragma unroll
    for (int i = 0; i < 4; i++) {
        int idx = tid + i*256;
        e[i] = (idx < NOUT) ? expf(v[i] - m2) : 0.f;
        sm += e[i];
    }
#pragma unroll
    for (int o = 16; o > 0; o >>= 1) sm += __shfl_xor_sync(0xffffffffu, sm, o);
    __syncthreads();
    if ((tid & 31) == 0) red[tid >> 5] = sm;
    __syncthreads();
    float tot = 0.f;
#pragma unroll
    for (int i = 0; i < 8; i++) tot += red[i];
    float inv = 1.f / tot;
#pragma unroll
    for (int i = 0; i < 4; i++) {
        int idx = tid + i*256;
        if (idx < NOUT) out[(size_t)row*NOUT + idx] = e[i] * inv;
    }
}

// ============================ host launcher =================================
extern "C" void kernel_launch(void* const* d_in, const int* in_sizes, int n_in,
                              void* d_out, int out_size) {
    (void)in_sizes; (void)n_in; (void)out_size;
    const float* x       = (const float*)d_in[0];
    const float* w_embed = (const float*)d_in[1];
    const float* b_embed = (const float*)d_in[2];
    const float* cls     = (const float*)d_in[3];
    const float* ln1_g   = (const float*)d_in[4];
    const float* ln1_b   = (const float*)d_in[5];
    const float* wq      = (const float*)d_in[6];
    const float* bq      = (const float*)d_in[7];
    const float* wk      = (const float*)d_in[8];
    const float* bk      = (const float*)d_in[9];
    const float* wv      = (const float*)d_in[10];
    const float* bv      = (const float*)d_in[11];
    const float* ln2_g   = (const float*)d_in[12];
    const float* ln2_b   = (const float*)d_in[13];
    const float* w1      = (const float*)d_in[14];
    const float* b1      = (const float*)d_in[15];
    const float* w2      = (const float*)d_in[16];
    const float* b2      = (const float*)d_in[17];
    const float* w_head  = (const float*)d_in[18];
    const float* b_head  = (const float*)d_in[19];
    float* out = (float*)d_out;

    float *p_tokens, *p_embf, *p_h;
    __half *p_hh, *p_mlph, *p_ph, *p_w1t, *p_w2t, *p_wembt;
    cudaGetSymbolAddress((void**)&p_tokens, g_tokens);
    cudaGetSymbolAddress((void**)&p_embf,   g_embf);
    cudaGetSymbolAddress((void**)&p_h,      g_h);
    cudaGetSymbolAddress((void**)&p_hh,     g_hh);
    cudaGetSymbolAddress((void**)&p_mlph,   g_mlph);
    cudaGetSymbolAddress((void**)&p_ph,     g_ph);
    cudaGetSymbolAddress((void**)&p_w1t,    g_w1t);
    cudaGetSymbolAddress((void**)&p_w2t,    g_w2t);
    cudaGetSymbolAddress((void**)&p_wembt,  g_wembt);

    cudaFuncSetAttribute(gemm_h<0,0>, cudaFuncAttributeMaxDynamicSharedMemorySize, GH_SMEM_BYTES);
    cudaFuncSetAttribute(gemm_h<1,2>, cudaFuncAttributeMaxDynamicSharedMemorySize, GH_SMEM_BYTES);
    cudaFuncSetAttribute(gemm_h<0,1>, cudaFuncAttributeMaxDynamicSharedMemorySize, GH_SMEM_BYTES);

    // ---- startup ----
    dim3 tb(32, 8);
    k_patchify<<<(MPAT*DIM + 255)/256, 256>>>(x, p_ph);
    k_transpose_h<<<dim3(DIM/32, DIM/32, 1), tb>>>(w_embed, p_wembt, DIM, DIM);
    k_transpose_h<<<dim3(MLPD/32, DIM/32, NLAYER), tb>>>(w1, p_w1t, DIM, MLPD);
    gemm_h<0,0><<<dim3(DIM/128, (MPAT+127)/128), 256, GH_SMEM_BYTES>>>(
        MPAT, DIM, p_ph, DIM, p_wembt, DIM, b_embed, p_embf, nullptr, DIM);
    k_transpose_h<<<dim3(DIM/32, MLPD/32, NLAYER), tb>>>(w2, p_w2t, MLPD, DIM);
    k_build_tokens<<<(MTOK*DIM + 255)/256, 256>>>(p_embf, cls);

    // ---- transformer layers ----
    const int softmax_rows = BATCH*NHEAD*SEQ;
    for (int l = 0; l < NLAYER; l++) {
        k_layernorm<<<MTOK, 256>>>(p_tokens, ln1_g + l*DIM, ln1_b + l*DIM, p_h, nullptr);
        k_qkv_tc<<<dim3((MTOK + 63)/64, NHEAD, 3), 128>>>(wq, wk, wv, bq, bk, bv, l);
        k_scores_tc<<<dim3(4, 4, BATCH*NHEAD), 128>>>();
        k_softmax_attn2<<<(softmax_rows + 7)/8, 256>>>();
        k_av_tc<<<dim3(4, BATCH*NHEAD), 128>>>();
        k_layernorm<<<MTOK, 256>>>(p_tokens, ln2_g + l*DIM, ln2_b + l*DIM, nullptr, p_hh);
        gemm_h<1,2><<<dim3(MLPD/128, (MTOK+127)/128), 256, GH_SMEM_BYTES>>>(
            MTOK, DIM, p_hh, DIM, p_w1t + (size_t)l*MLPD*DIM, DIM,
            b1 + (size_t)l*MLPD, nullptr, p_mlph, MLPD);
        gemm_h<0,1><<<dim3(DIM/128, (MTOK+127)/128), 256, GH_SMEM_BYTES>>>(
            MTOK, MLPD, p_mlph, MLPD, p_w2t + (size_t)l*DIM*MLPD, MLPD,
            b2 + (size_t)l*DIM, p_tokens, nullptr, DIM);
    }

    // ---- classification head + softmax ----
    sgemm128<0, false><<<dim3(8, 1), 256>>>(BATCH, NOUT, DIM, p_tokens, SEQ*DIM,
                                            w_head, NOUT, b_head, p_embf, NOUT);
    k_softmax_out<<<BATCH, 256>>>(p_embf, out);
}

// round 15
// speedup vs baseline: 1.5359x; 1.0213x over previous
#include <cuda_runtime.h>
#include <cuda_fp16.h>
#include <math.h>
#include <stdint.h>
#include <mma.h>

using namespace nvcuda;

#define BATCH 32
#define SEQ 197
#define DIM 768
#define NHEAD 12
#define DHEAD 64
#define NLAYER 12
#define MLPD 3072
#define NOUT 1000
#define NPATCH 196
#define MTOK (BATCH*SEQ)        /* 6304 */
#define MPAT (BATCH*NPATCH)     /* 6272 */
#define ASTRIDE 208             /* padded attn row stride */

// ---------------- scratch (device globals) ----------------------------------
__device__ float  g_tokens[MTOK*DIM];
__device__ float  g_embf[MPAT*DIM];
__device__ float  g_attn[(size_t)BATCH*NHEAD*SEQ*ASTRIDE];
__device__ __half g_hh[MTOK*DIM];           // LN1 out (qkv in), later LN2 out (MLP1 in)
__device__ __half g_qh[MTOK*DIM];
__device__ __half g_kh[MTOK*DIM];
__device__ __half g_vh[MTOK*DIM];
__device__ __half g_mlph[(size_t)MTOK*MLPD];
__device__ __half g_ph[(size_t)MPAT*DIM];
__device__ __half g_w1t[(size_t)NLAYER*MLPD*DIM];   // [l][N=3072][K=768]
__device__ __half g_w2t[(size_t)NLAYER*DIM*MLPD];   // [l][N=768][K=3072]
__device__ __half g_wembt[DIM*DIM];                 // [N=768][K=768]

__device__ __forceinline__ float gelu_exact(float x) {
    return 0.5f * x * (1.f + erff(x * 0.70710678118654752f));
}
__device__ __forceinline__ float r32(float x) { return wmma::__float_to_tf32(x); }
__device__ __forceinline__ uint32_t s2u(const void* p) {
    uint32_t a;
    asm("{ .reg .u64 t; cvta.to.shared.u64 t, %1; cvt.u32.u64 %0, t; }" : "=r"(a) : "l"(p));
    return a;
}
__device__ __forceinline__ void cp16(uint32_t dst, const void* src, bool pred) {
    int sz = pred ? 16 : 0;
    asm volatile("cp.async.ca.shared.global [%0], [%1], 16, %2;"
                 :: "r"(dst), "l"(src), "r"(sz));
}
#define CP_COMMIT() asm volatile("cp.async.commit_group;" ::: "memory")
#define CP_WAIT0()  asm volatile("cp.async.wait_group 0;" ::: "memory")

// half4 (uint2) -> float4 convert
__device__ __forceinline__ float4 h4_to_f4(uint2 raw) {
    __half2 h0 = *(__half2*)&raw.x;
    __half2 h1 = *(__half2*)&raw.y;
    float2 f0 = __half22float2(h0);
    float2 f1 = __half22float2(h1);
    return make_float4(f0.x, f0.y, f1.x, f1.y);
}

// ================= fp16 wmma GEMM: 256 thr, 8 warps (2x4), warp 64x32 =======
// (verified R10)
#define GH_LDS 72
#define GH_BUF (128*GH_LDS)
#define GH_LDE 132
#define GH_SMEM_BYTES (4*GH_BUF*2 > 128*GH_LDE*4 ? 4*GH_BUF*2 : 128*GH_LDE*4)

template<int ACT, int OUTMODE>
__global__ void __launch_bounds__(256, 2)
gemm_h(int M, int K,
       const __half* __restrict__ A, int lda,
       const __half* __restrict__ Bt, int ldb,
       const float* __restrict__ bias,
       float* __restrict__ Cf, __half* __restrict__ Ch, int ldc) {
    extern __shared__ __align__(128) __half smh[];
    const int tid = threadIdx.x;
    const int wid = tid >> 5;
    const int row0 = blockIdx.y * 128, col0 = blockIdx.x * 128;
    const int wm = wid & 1, wn = wid >> 1;

    wmma::fragment<wmma::accumulator, 16, 16, 16, float> acc[4][2];
#pragma unroll
    for (int i = 0; i < 4; i++)
#pragma unroll
        for (int j = 0; j < 2; j++) wmma::fill_fragment(acc[i][j], 0.f);

    const int nc = K >> 6;
    const int r = tid >> 3, c = tid & 7;

    {   // stage 0
        __half* As = smh;
        __half* Bs = smh + 2*GH_BUF;
#pragma unroll
        for (int i = 0; i < 4; i++) {
            int rr = r + i * 32;
            cp16(s2u(&As[rr * GH_LDS + c * 8]),
                 A + (size_t)(row0 + rr) * lda + c * 8, (row0 + rr) < M);
            cp16(s2u(&Bs[rr * GH_LDS + c * 8]),
                 Bt + (size_t)(col0 + rr) * ldb + c * 8, true);
        }
        CP_COMMIT();
    }

    for (int kc = 0; kc < nc; kc++) {
        const int cur = kc & 1;
        CP_WAIT0();
        __syncthreads();
        if (kc + 1 < nc) {
            const int nxt = 1 - cur;
            const int ko = (kc + 1) * 64;
            __half* As = smh + nxt * GH_BUF;
            __half* Bs = smh + 2*GH_BUF + nxt * GH_BUF;
#pragma unroll
            for (int i = 0; i < 4; i++) {
                int rr = r + i * 32;
                cp16(s2u(&As[rr * GH_LDS + c * 8]),
                     A + (size_t)(row0 + rr) * lda + ko + c * 8, (row0 + rr) < M);
                cp16(s2u(&Bs[rr * GH_LDS + c * 8]),
                     Bt + (size_t)(col0 + rr) * ldb + ko + c * 8, true);
            }
            CP_COMMIT();
        }
        const __half* As = smh + cur * GH_BUF;
        const __half* Bs = smh + 2*GH_BUF + cur * GH_BUF;
#pragma unroll
        for (int ks = 0; ks < 4; ks++) {
            wmma::fragment<wmma::matrix_a, 16, 16, 16, __half, wmma::row_major> af[4];
#pragma unroll
            for (int i = 0; i < 4; i++)
                wmma::load_matrix_sync(af[i], &As[(wm*64 + i*16) * GH_LDS + ks*16], GH_LDS);
#pragma unroll
            for (int j = 0; j < 2; j++) {
                wmma::fragment<wmma::matrix_b, 16, 16, 16, __half, wmma::col_major> bf;
                wmma::load_matrix_sync(bf, &Bs[(wn*32 + j*16) * GH_LDS + ks*16], GH_LDS);
#pragma unroll
                for (int i = 0; i < 4; i++)
                    wmma::mma_sync(acc[i][j], af[i], bf, acc[i][j]);
            }
        }
    }

    __syncthreads();
    float* Epi = (float*)smh;
#pragma unroll
    for (int i = 0; i < 4; i++)
#pragma unroll
        for (int j = 0; j < 2; j++)
            wmma::store_matrix_sync(&Epi[(wm*64 + i*16) * GH_LDE + wn*32 + j*16],
                                    acc[i][j], GH_LDE, wmma::mem_row_major);
    __syncthreads();
#pragma unroll 4
    for (int it = 0; it < 16; it++) {
        int l = it * 256 + tid;
        int rr = l >> 5, c4 = l & 31;
        int gr = row0 + rr;
        if (gr >= M) continue;
        float4 v = *(float4*)&Epi[rr * GH_LDE + c4 * 4];
        int gc = col0 + c4 * 4;
        v.x += bias[gc+0]; v.y += bias[gc+1]; v.z += bias[gc+2]; v.w += bias[gc+3];
        if (ACT == 1) {
            v.x = gelu_exact(v.x); v.y = gelu_exact(v.y);
            v.z = gelu_exact(v.z); v.w = gelu_exact(v.w);
        }
        if (OUTMODE == 2) {
            __half2 h0 = __floats2half2_rn(v.x, v.y);
            __half2 h1 = __floats2half2_rn(v.z, v.w);
            uint2 pk = make_uint2(*(uint32_t*)&h0, *(uint32_t*)&h1);
            *(uint2*)(Ch + (size_t)gr * ldc + gc) = pk;
        } else {
            float* cp = Cf + (size_t)gr * ldc + gc;
            if (OUTMODE == 1) {
                float4 o = *(const float4*)cp;
                v.x += o.x; v.y += o.y; v.z += o.z; v.w += o.w;
            }
            *(float4*)cp = v;
        }
    }
}

// ---------------- QKV projection (tf32 compute; half in/out) ----------------
__global__ void __launch_bounds__(128)
k_qkv_tc(const float* __restrict__ wq, const float* __restrict__ wk,
         const float* __restrict__ wv, const float* __restrict__ bq,
         const float* __restrict__ bk, const float* __restrict__ bv, int l) {
    __shared__ float Hs[64][68];
    __shared__ float Ws[64][68];
    __shared__ float Epi[64][68];
    int head = blockIdx.y, which = blockIdx.z;
    const float* W; const float* bias; __half* out;
    if (which == 0)      { W = wq; bias = bq; out = g_qh; }
    else if (which == 1) { W = wk; bias = bk; out = g_kh; }
    else                 { W = wv; bias = bv; out = g_vh; }
    W    += ((size_t)l*NHEAD + head) * DHEAD * DHEAD;
    bias += ((size_t)l*NHEAD + head) * DHEAD;
    const int m0 = blockIdx.x * 64;
    const int tid = threadIdx.x, wid = tid >> 5;

#pragma unroll
    for (int i = 0; i < 8; i++) {
        int ll = i * 128 + tid;
        int rr = ll >> 4, c4 = ll & 15;
        float4 v = make_float4(0.f,0.f,0.f,0.f);
        if (m0 + rr < MTOK) {
            uint2 raw = *(const uint2*)(g_hh + (size_t)(m0 + rr)*DIM + head*DHEAD + c4*4);
            v = h4_to_f4(raw);
        }
        *(float4*)&Hs[rr][c4*4] = v;
        float4 w = *(const float4*)(W + rr*64 + c4*4);
        w.x = r32(w.x); w.y = r32(w.y); w.z = r32(w.z); w.w = r32(w.w);
        *(float4*)&Ws[rr][c4*4] = w;
    }
    __syncthreads();

    wmma::fragment<wmma::accumulator, 16, 16, 8, float> acc[4];
#pragma unroll
    for (int j = 0; j < 4; j++) wmma::fill_fragment(acc[j], 0.f);
#pragma unroll
    for (int ks = 0; ks < 8; ks++) {
        wmma::fragment<wmma::matrix_a, 16, 16, 8, wmma::precision::tf32, wmma::row_major> af;
        wmma::load_matrix_sync(af, &Hs[wid*16][ks*8], 68);
#pragma unroll
        for (int j = 0; j < 4; j++) {
            wmma::fragment<wmma::matrix_b, 16, 16, 8, wmma::precision::tf32, wmma::row_major> bf;
            wmma::load_matrix_sync(bf, &Ws[ks*8][j*16], 68);
            wmma::mma_sync(acc[j], af, bf, acc[j]);
        }
    }
#pragma unroll
    for (int j = 0; j < 4; j++)
        wmma::store_matrix_sync(&Epi[wid*16][j*16], acc[j], 68, wmma::mem_row_major);
    __syncthreads();
#pragma unroll
    for (int i = 0; i < 8; i++) {
        int ll = i * 128 + tid;
        int rr = ll >> 4, c4 = ll & 15;
        int gr = m0 + rr;
        if (gr >= MTOK) continue;
        float4 v = *(float4*)&Epi[rr][c4*4];
        __half2 h0 = __floats2half2_rn(v.x + bias[c4*4+0], v.y + bias[c4*4+1]);
        __half2 h1 = __floats2half2_rn(v.z + bias[c4*4+2], v.w + bias[c4*4+3]);
        uint2 pk = make_uint2(*(uint32_t*)&h0, *(uint32_t*)&h1);
        *(uint2*)(out + (size_t)gr*DIM + head*DHEAD + c4*4) = pk;
    }
}

// ---------------- attention scores (tf32 compute; half Q/K in) --------------
__global__ void __launch_bounds__(128)
k_scores_tc() {
    __shared__ float Qs[64][68];
    __shared__ float Ks[64][68];
    __shared__ float Epi[64][68];
    const int bz = blockIdx.z;
    const int b = bz / NHEAD, h = bz % NHEAD;
    const int t0 = blockIdx.x * 64, s0 = blockIdx.y * 64;
    const int tid = threadIdx.x, wid = tid >> 5;
    const __half* Q = g_qh + (size_t)b*SEQ*DIM + h*DHEAD;
    const __half* K = g_kh + (size_t)b*SEQ*DIM + h*DHEAD;

#pragma unroll
    for (int i = 0; i < 8; i++) {
        int ll = i * 128 + tid;
        int rr = ll >> 4, c4 = ll & 15;
        float4 q = make_float4(0.f,0.f,0.f,0.f);
        if (s0 + rr < SEQ)
            q = h4_to_f4(*(const uint2*)(Q + (size_t)(s0 + rr)*DIM + c4*4));
        *(float4*)&Qs[rr][c4*4] = q;
        float4 k = make_float4(0.f,0.f,0.f,0.f);
        if (t0 + rr < SEQ)
            k = h4_to_f4(*(const uint2*)(K + (size_t)(t0 + rr)*DIM + c4*4));
        *(float4*)&Ks[rr][c4*4] = k;
    }
    __syncthreads();

    wmma::fragment<wmma::accumulator, 16, 16, 8, float> acc[4];
#pragma unroll
    for (int j = 0; j < 4; j++) wmma::fill_fragment(acc[j], 0.f);
#pragma unroll
    for (int ks = 0; ks < 8; ks++) {
        wmma::fragment<wmma::matrix_a, 16, 16, 8, wmma::precision::tf32, wmma::row_major> af;
        wmma::load_matrix_sync(af, &Qs[wid*16][ks*8], 68);
#pragma unroll
        for (int j = 0; j < 4; j++) {
            wmma::fragment<wmma::matrix_b, 16, 16, 8, wmma::precision::tf32, wmma::col_major> bf;
            wmma::load_matrix_sync(bf, &Ks[j*16][ks*8], 68);
            wmma::mma_sync(acc[j], af, bf, acc[j]);
        }
    }
#pragma unroll
    for (int j = 0; j < 4; j++)
        wmma::store_matrix_sync(&Epi[wid*16][j*16], acc[j], 68, wmma::mem_row_major);
    __syncthreads();
#pragma unroll
    for (int i = 0; i < 8; i++) {
        int ll = i * 128 + tid;
        int rr = ll >> 4, c4 = ll & 15;
        int s = s0 + rr;
        if (s >= SEQ) continue;
        int t = t0 + c4*4;
        if (t >= ASTRIDE) continue;
        float4 v = *(float4*)&Epi[rr][c4*4];
        v.x *= 0.125f; v.y *= 0.125f; v.z *= 0.125f; v.w *= 0.125f;
        float* p = g_attn + ((size_t)bz*SEQ + s)*ASTRIDE + t;
        if (t + 3 < SEQ) {
            *(float4*)p = v;
        } else {
            float vv[4] = {v.x, v.y, v.z, v.w};
#pragma unroll
            for (int e = 0; e < 4; e++) {
                int tt = t + e;
                if (tt < ASTRIDE) p[e] = (tt < SEQ) ? vv[e] : 0.f;
            }
        }
    }
}

// ---------------- softmax: warp-per-row, 8 rows/block (verified) -----------
__global__ void __launch_bounds__(256)
k_softmax_attn2() {
    int gw = blockIdx.x * 8 + (threadIdx.x >> 5);
    if (gw >= BATCH*NHEAD*SEQ) return;
    float* p = g_attn + (size_t)gw * ASTRIDE;
    int lane = threadIdx.x & 31;
    float v[7];
    float mx = -1e30f;
#pragma unroll
    for (int i = 0; i < 7; i++) {
        int t = lane + i*32;
        v[i] = (t < SEQ) ? p[t] : -1e30f;
        mx = fmaxf(mx, v[i]);
    }
#pragma unroll
    for (int o = 16; o > 0; o >>= 1) mx = fmaxf(mx, __shfl_xor_sync(0xffffffffu, mx, o));
    float sm = 0.f;
#pragma unroll
    for (int i = 0; i < 7; i++) {
        v[i] = (lane + i*32 < SEQ) ? expf(v[i] - mx) : 0.f;
        sm += v[i];
    }
#pragma unroll
    for (int o = 16; o > 0; o >>= 1) sm += __shfl_xor_sync(0xffffffffu, sm, o);
    float inv = 1.f / sm;
#pragma unroll
    for (int i = 0; i < 7; i++) {
        int t = lane + i*32;
        if (t < SEQ) p[t] = r32(v[i] * inv);
    }
}

// ---------------- o = attn @ v (tf32 compute; half V in), fused residual ---
__global__ void __launch_bounds__(128)
k_av_tc() {
    __shared__ float Ps[64][20];
    __shared__ float Vs[16][68];
    __shared__ float Epi[64][68];
    const int bz = blockIdx.y;
    const int b = bz / NHEAD, h = bz % NHEAD;
    const int s0 = blockIdx.x * 64;
    const int tid = threadIdx.x, wid = tid >> 5;
    const float* Pb = g_attn + (size_t)bz*SEQ*ASTRIDE;
    const __half* V = g_vh + (size_t)b*SEQ*DIM + h*DHEAD;

    wmma::fragment<wmma::accumulator, 16, 16, 8, float> acc[4];
#pragma unroll
    for (int j = 0; j < 4; j++) wmma::fill_fragment(acc[j], 0.f);

    for (int kc = 0; kc < 13; kc++) {
#pragma unroll
        for (int i = 0; i < 2; i++) {
            int ll = i * 128 + tid;
            int rr = ll >> 2, cc = ll & 3;
            int s = s0 + rr;
            float4 pv = make_float4(0.f,0.f,0.f,0.f);
            if (s < SEQ) pv = *(const float4*)(Pb + (size_t)s*ASTRIDE + kc*16 + cc*4);
            *(float4*)&Ps[rr][cc*4] = pv;
            int l2 = i * 128 + tid;
            int vr = l2 >> 4, vc = l2 & 15;
            int t = kc*16 + vr;
            float4 vv = make_float4(0.f,0.f,0.f,0.f);
            if (t < SEQ)
                vv = h4_to_f4(*(const uint2*)(V + (size_t)t*DIM + vc*4));
            *(float4*)&Vs[vr][vc*4] = vv;
        }
        __syncthreads();
#pragma unroll
        for (int ks = 0; ks < 2; ks++) {
            wmma::fragment<wmma::matrix_a, 16, 16, 8, wmma::precision::tf32, wmma::row_major> af;
            wmma::load_matrix_sync(af, &Ps[wid*16][ks*8], 20);
#pragma unroll
            for (int j = 0; j < 4; j++) {
                wmma::fragment<wmma::matrix_b, 16, 16, 8, wmma::precision::tf32, wmma::row_major> bf;
                wmma::load_matrix_sync(bf, &Vs[ks*8][j*16], 68);
                wmma::mma_sync(acc[j], af, bf, acc[j]);
            }
        }
        __syncthreads();
    }
#pragma unroll
    for (int j = 0; j < 4; j++)
        wmma::store_matrix_sync(&Epi[wid*16][j*16], acc[j], 68, wmma::mem_row_major);
    __syncthreads();
#pragma unroll
    for (int i = 0; i < 8; i++) {
        int ll = i * 128 + tid;
        int rr = ll >> 4, c4 = ll & 15;
        int s = s0 + rr;
        if (s >= SEQ) continue;
        float* tp = g_tokens + ((size_t)b*SEQ + s)*DIM + h*DHEAD + c4*4;
        float4 o = *(const float4*)tp;
        float4 v = *(float4*)&Epi[rr][c4*4];
        o.x += v.x; o.y += v.y; o.z += v.z; o.w += v.w;
        *(float4*)tp = o;
    }
}

// ---------------- transpose fp32 -> half [C,R] ------------------------------
__global__ void k_transpose_h(const float* __restrict__ in, __half* __restrict__ out,
                              int R, int C) {
    __shared__ float t[32][33];
    size_t lo = (size_t)blockIdx.z * R * C;
    int c0 = blockIdx.x * 32, r0 = blockIdx.y * 32;
#pragma unroll
    for (int i = 0; i < 4; i++) {
        int r = r0 + threadIdx.y + i * 8;
        int c = c0 + threadIdx.x;
        t[threadIdx.y + i * 8][threadIdx.x] = in[lo + (size_t)r * C + c];
    }
    __syncthreads();
#pragma unroll
    for (int i = 0; i < 4; i++) {
        int c = c0 + threadIdx.y + i * 8;
        int r = r0 + threadIdx.x;
        out[lo + (size_t)c * R + r] = __float2half(t[threadIdx.x][threadIdx.y + i * 8]);
    }
}

// ---------------- patchify (half out) ---------------------------------------
__global__ void k_patchify(const float* __restrict__ x, __half* __restrict__ out) {
    int idx = blockIdx.x * blockDim.x + threadIdx.x;
    const int total = MPAT * DIM;
    if (idx >= total) return;
    int e   = idx % DIM;
    int row = idx / DIM;
    int b  = row / NPATCH, p = row % NPATCH;
    int pi = p / 14, pj = p % 14;
    int c  = e / 256, r = e % 256;
    int ph = r / 16,  pw = r % 16;
    out[idx] = __float2half(x[(((b*3 + c)*224) + pi*16 + ph)*224 + pj*16 + pw]);
}

// ---------------- build tokens -----------------------------------------------
__global__ void k_build_tokens(const float* __restrict__ emb, const float* __restrict__ cls) {
    int idx = blockIdx.x * blockDim.x + threadIdx.x;
    if (idx >= MTOK * DIM) return;
    int d   = idx % DIM;
    int rem = idx / DIM;
    int s = rem % SEQ;
    int b = rem / SEQ;
    int jj = d & ~1;
    float p   = expf(-((float)jj / (float)DIM) * 9.210340371976184f);
    float arg = (float)s * p;
    float pe  = (d & 1) ? cosf(arg) : sinf(arg);
    float base = (s == 0) ? cls[d] : emb[(b*NPATCH + s - 1)*DIM + d];
    g_tokens[(size_t)b*SEQ*DIM + (size_t)s*DIM + d] = base + pe;
}

// ---------------- layernorm: writes fp32(r32) and/or half -------------------
__global__ void k_layernorm(const float* __restrict__ in, const float* __restrict__ gam,
                            const float* __restrict__ bet,
                            float* __restrict__ outf, __half* __restrict__ outh) {
    int row = blockIdx.x;
    int tid = threadIdx.x;
    const float* xr = in + (size_t)row * DIM;
    float xs[3];
    float s = 0.f;
#pragma unroll
    for (int i = 0; i < 3; i++) { xs[i] = xr[tid + i*256]; s += xs[i]; }
    __shared__ float red[8];
#pragma unroll
    for (int o = 16; o > 0; o >>= 1) s += __shfl_xor_sync(0xffffffffu, s, o);
    if ((tid & 31) == 0) red[tid >> 5] = s;
    __syncthreads();
    float mu = 0.f;
    {
        float tot = 0.f;
#pragma unroll
        for (int i = 0; i < 8; i++) tot += red[i];
        mu = tot * (1.f / DIM);
    }
    __syncthreads();
    float v = 0.f;
#pragma unroll
    for (int i = 0; i < 3; i++) { float dlt = xs[i] - mu; v += dlt * dlt; }
#pragma unroll
    for (int o = 16; o > 0; o >>= 1) v += __shfl_xor_sync(0xffffffffu, v, o);
    if ((tid & 31) == 0) red[tid >> 5] = v;
    __syncthreads();
    float var = 0.f;
#pragma unroll
    for (int i = 0; i < 8; i++) var += red[i];
    var *= (1.f / DIM);
    float rstd = rsqrtf(var + 1e-5f);
#pragma unroll
    for (int i = 0; i < 3; i++) {
        int d = tid + i*256;
        float y = (xs[i] - mu) * rstd * gam[d] + bet[d];
        if (outf) outf[(size_t)row*DIM + d] = r32(y);
        if (outh) outh[(size_t)row*DIM + d] = __float2half(y);
    }
}

// ---------------- SIMT SGEMM (tiny head GEMM) ------------------------------
template<int ACT, bool ACCUM>
__global__ void sgemm128(int M, int N, int K,
                         const float* __restrict__ A, int lda,
                         const float* __restrict__ Bm, int ldb,
                         const float* __restrict__ bias,
                         float* __restrict__ C, int ldc) {
    __shared__ float As[8][128];
    __shared__ float Bs[8][132];
    int tid = threadIdx.x;
    int tx = tid & 15, ty = tid >> 4;
    int row0 = blockIdx.y * 128, col0 = blockIdx.x * 128;
    float acc[8][8];
#pragma unroll
    for (int i = 0; i < 8; i++)
#pragma unroll
        for (int j = 0; j < 8; j++) acc[i][j] = 0.f;

    for (int kk = 0; kk < K; kk += 8) {
        {
            int idx = tid * 4;
            int r = idx >> 3, c = idx & 7;
            float4 v = make_float4(0.f, 0.f, 0.f, 0.f);
            int gr = row0 + r;
            if (gr < M) v = *(const float4*)(A + (size_t)gr * lda + kk + c);
            As[c+0][r] = v.x; As[c+1][r] = v.y; As[c+2][r] = v.z; As[c+3][r] = v.w;
        }
        {
            int idx = tid * 4;
            int r = idx >> 7, c = idx & 127;
            int gc = col0 + c;
            float4 v;
            if (gc + 3 < N) {
                v = *(const float4*)(Bm + (size_t)(kk + r) * ldb + gc);
            } else {
                float t0 = (gc+0 < N) ? Bm[(size_t)(kk+r)*ldb + gc+0] : 0.f;
                float t1 = (gc+1 < N) ? Bm[(size_t)(kk+r)*ldb + gc+1] : 0.f;
                float t2 = (gc+2 < N) ? Bm[(size_t)(kk+r)*ldb + gc+2] : 0.f;
                float t3 = (gc+3 < N) ? Bm[(size_t)(kk+r)*ldb + gc+3] : 0.f;
                v = make_float4(t0, t1, t2, t3);
            }
            *(float4*)&Bs[r][c] = v;
        }
        __syncthreads();
#pragma unroll
        for (int k = 0; k < 8; k++) {
            float a[8], b[8];
            *(float4*)&a[0] = *(const float4*)&As[k][ty*8];
            *(float4*)&a[4] = *(const float4*)&As[k][ty*8 + 4];
            *(float4*)&b[0] = *(const float4*)&Bs[k][tx*8];
            *(float4*)&b[4] = *(const float4*)&Bs[k][tx*8 + 4];
#pragma unroll
            for (int i = 0; i < 8; i++)
#pragma unroll
                for (int j = 0; j < 8; j++)
                    acc[i][j] = fmaf(a[i], b[j], acc[i][j]);
        }
        __syncthreads();
    }
#pragma unroll
    for (int i = 0; i < 8; i++) {
        int gr = row0 + ty*8 + i;
        if (gr >= M) continue;
#pragma unroll
        for (int j = 0; j < 8; j++) {
            int gc = col0 + tx*8 + j;
            if (gc >= N) continue;
            float v = acc[i][j] + (bias ? bias[gc] : 0.f);
            if (ACT == 1) v = gelu_exact(v);
            if (ACCUM) C[(size_t)gr*ldc + gc] += v;
            else       C[(size_t)gr*ldc + gc]  = v;
        }
    }
}

// ---------------- output softmax --------------------------------------------
__global__ void k_softmax_out(const float* __restrict__ logits, float* __restrict__ out) {
    int row = blockIdx.x;
    int tid = threadIdx.x;
    const float* p = logits + (size_t)row * NOUT;
    float v[4];
    float mx = -1e30f;
#pragma unroll
    for (int i = 0; i < 4; i++) {
        int idx = tid + i*256;
        v[i] = (idx < NOUT) ? p[idx] : -1e30f;
        mx = fmaxf(mx, v[i]);
    }
    __shared__ float red[8];
#pragma unroll
    for (int o = 16; o > 0; o >>= 1) mx = fmaxf(mx, __shfl_xor_sync(0xffffffffu, mx, o));
    if ((tid & 31) == 0) red[tid >> 5] = mx;
    __syncthreads();
    float m2 = red[0];
#pragma unroll
    for (int i = 1; i < 8; i++) m2 = fmaxf(m2, red[i]);
    float e[4], sm = 0.f;
#pragma unroll
    for (int i = 0; i < 4; i++) {
        int idx = tid + i*256;
        e[i] = (idx < NOUT) ? expf(v[i] - m2) : 0.f;
        sm += e[i];
    }
#pragma unroll
    for (int o = 16; o > 0; o >>= 1) sm += __shfl_xor_sync(0xffffffffu, sm, o);
    __syncthreads();
    if ((tid & 31) == 0) red[tid >> 5] = sm;
    __syncthreads();
    float tot = 0.f;
#pragma unroll
    for (int i = 0; i < 8; i++) tot += red[i];
    float inv = 1.f / tot;
#pragma unroll
    for (int i = 0; i < 4; i++) {
        int idx = tid + i*256;
        if (idx < NOUT) out[(size_t)row*NOUT + idx] = e[i] * inv;
    }
}

// ============================ host launcher =================================
extern "C" void kernel_launch(void* const* d_in, const int* in_sizes, int n_in,
                              void* d_out, int out_size) {
    (void)in_sizes; (void)n_in; (void)out_size;
    const float* x       = (const float*)d_in[0];
    const float* w_embed = (const float*)d_in[1];
    const float* b_embed = (const float*)d_in[2];
    const float* cls     = (const float*)d_in[3];
    const float* ln1_g   = (const float*)d_in[4];
    const float* ln1_b   = (const float*)d_in[5];
    const float* wq      = (const float*)d_in[6];
    const float* bq      = (const float*)d_in[7];
    const float* wk      = (const float*)d_in[8];
    const float* bk      = (const float*)d_in[9];
    const float* wv      = (const float*)d_in[10];
    const float* bv      = (const float*)d_in[11];
    const float* ln2_g   = (const float*)d_in[12];
    const float* ln2_b   = (const float*)d_in[13];
    const float* w1      = (const float*)d_in[14];
    const float* b1      = (const float*)d_in[15];
    const float* w2      = (const float*)d_in[16];
    const float* b2      = (const float*)d_in[17];
    const float* w_head  = (const float*)d_in[18];
    const float* b_head  = (const float*)d_in[19];
    float* out = (float*)d_out;

    float *p_tokens, *p_embf;
    __half *p_hh, *p_mlph, *p_ph, *p_w1t, *p_w2t, *p_wembt;
    cudaGetSymbolAddress((void**)&p_tokens, g_tokens);
    cudaGetSymbolAddress((void**)&p_embf,   g_embf);
    cudaGetSymbolAddress((void**)&p_hh,     g_hh);
    cudaGetSymbolAddress((void**)&p_mlph,   g_mlph);
    cudaGetSymbolAddress((void**)&p_ph,     g_ph);
    cudaGetSymbolAddress((void**)&p_w1t,    g_w1t);
    cudaGetSymbolAddress((void**)&p_w2t,    g_w2t);
    cudaGetSymbolAddress((void**)&p_wembt,  g_wembt);

    cudaFuncSetAttribute(gemm_h<0,0>, cudaFuncAttributeMaxDynamicSharedMemorySize, GH_SMEM_BYTES);
    cudaFuncSetAttribute(gemm_h<1,2>, cudaFuncAttributeMaxDynamicSharedMemorySize, GH_SMEM_BYTES);
    cudaFuncSetAttribute(gemm_h<0,1>, cudaFuncAttributeMaxDynamicSharedMemorySize, GH_SMEM_BYTES);

    // ---- startup ----
    dim3 tb(32, 8);
    k_patchify<<<(MPAT*DIM + 255)/256, 256>>>(x, p_ph);
    k_transpose_h<<<dim3(DIM/32, DIM/32, 1), tb>>>(w_embed, p_wembt, DIM, DIM);
    k_transpose_h<<<dim3(MLPD/32, DIM/32, NLAYER), tb>>>(w1, p_w1t, DIM, MLPD);
    gemm_h<0,0><<<dim3(DIM/128, (MPAT+127)/128), 256, GH_SMEM_BYTES>>>(
        MPAT, DIM, p_ph, DIM, p_wembt, DIM, b_embed, p_embf, nullptr, DIM);
    k_transpose_h<<<dim3(DIM/32, MLPD/32, NLAYER), tb>>>(w2, p_w2t, MLPD, DIM);
    k_build_tokens<<<(MTOK*DIM + 255)/256, 256>>>(p_embf, cls);

    // ---- transformer layers ----
    const int softmax_rows = BATCH*NHEAD*SEQ;
    for (int l = 0; l < NLAYER; l++) {
        k_layernorm<<<MTOK, 256>>>(p_tokens, ln1_g + l*DIM, ln1_b + l*DIM, nullptr, p_hh);
        k_qkv_tc<<<dim3((MTOK + 63)/64, NHEAD, 3), 128>>>(wq, wk, wv, bq, bk, bv, l);
        k_scores_tc<<<dim3(4, 4, BATCH*NHEAD), 128>>>();
        k_softmax_attn2<<<(softmax_rows + 7)/8, 256>>>();
        k_av_tc<<<dim3(4, BATCH*NHEAD), 128>>>();
        k_layernorm<<<MTOK, 256>>>(p_tokens, ln2_g + l*DIM, ln2_b + l*DIM, nullptr, p_hh);
        gemm_h<1,2><<<dim3(MLPD/128, (MTOK+127)/128), 256, GH_SMEM_BYTES>>>(
            MTOK, DIM, p_hh, DIM, p_w1t + (size_t)l*MLPD*DIM, DIM,
            b1 + (size_t)l*MLPD, nullptr, p_mlph, MLPD);
        gemm_h<0,1><<<dim3(DIM/128, (MTOK+127)/128), 256, GH_SMEM_BYTES>>>(
            MTOK, MLPD, p_mlph, MLPD, p_w2t + (size_t)l*DIM*MLPD, MLPD,
            b2 + (size_t)l*DIM, p_tokens, nullptr, DIM);
    }

    // ---- classification head + softmax ----
    sgemm128<0, false><<<dim3(8, 1), 256>>>(BATCH, NOUT, DIM, p_tokens, SEQ*DIM,
                                            w_head, NOUT, b_head, p_embf, NOUT);
    k_softmax_out<<<BATCH, 256>>>(p_embf, out);
}

// round 16
// speedup vs baseline: 1.5627x; 1.0174x over previous
#include <cuda_runtime.h>
#include <cuda_fp16.h>
#include <math.h>
#include <stdint.h>
#include <mma.h>

using namespace nvcuda;

#define BATCH 32
#define SEQ 197
#define DIM 768
#define NHEAD 12
#define DHEAD 64
#define NLAYER 12
#define MLPD 3072
#define NOUT 1000
#define NPATCH 196
#define MTOK (BATCH*SEQ)        /* 6304 */
#define MPAT (BATCH*NPATCH)     /* 6272 */
#define ASTRIDE 208             /* padded attn row stride */

// ---------------- scratch (device globals) ----------------------------------
__device__ float  g_tokens[MTOK*DIM];
__device__ float  g_embf[MPAT*DIM];
__device__ __half g_attnh[(size_t)BATCH*NHEAD*SEQ*ASTRIDE];
__device__ __half g_hh[MTOK*DIM];           // LN1 out (qkv in), later LN2 out (MLP1 in)
__device__ __half g_qh[MTOK*DIM];
__device__ __half g_kh[MTOK*DIM];
__device__ __half g_vh[MTOK*DIM];
__device__ __half g_mlph[(size_t)MTOK*MLPD];
__device__ __half g_ph[(size_t)MPAT*DIM];
__device__ __half g_w1t[(size_t)NLAYER*MLPD*DIM];   // [l][N=3072][K=768]
__device__ __half g_w2t[(size_t)NLAYER*DIM*MLPD];   // [l][N=768][K=3072]
__device__ __half g_wembt[DIM*DIM];                 // [N=768][K=768]

__device__ __forceinline__ float gelu_exact(float x) {
    return 0.5f * x * (1.f + erff(x * 0.70710678118654752f));
}
__device__ __forceinline__ float r32(float x) { return wmma::__float_to_tf32(x); }
__device__ __forceinline__ uint32_t s2u(const void* p) {
    uint32_t a;
    asm("{ .reg .u64 t; cvta.to.shared.u64 t, %1; cvt.u32.u64 %0, t; }" : "=r"(a) : "l"(p));
    return a;
}
__device__ __forceinline__ void cp16(uint32_t dst, const void* src, bool pred) {
    int sz = pred ? 16 : 0;
    asm volatile("cp.async.ca.shared.global [%0], [%1], 16, %2;"
                 :: "r"(dst), "l"(src), "r"(sz));
}
#define CP_COMMIT() asm volatile("cp.async.commit_group;" ::: "memory")
#define CP_WAIT0()  asm volatile("cp.async.wait_group 0;" ::: "memory")

// half4 (uint2) -> float4 convert
__device__ __forceinline__ float4 h4_to_f4(uint2 raw) {
    __half2 h0 = *(__half2*)&raw.x;
    __half2 h1 = *(__half2*)&raw.y;
    float2 f0 = __half22float2(h0);
    float2 f1 = __half22float2(h1);
    return make_float4(f0.x, f0.y, f1.x, f1.y);
}
__device__ __forceinline__ uint2 f4_to_h4(float4 v) {
    __half2 h0 = __floats2half2_rn(v.x, v.y);
    __half2 h1 = __floats2half2_rn(v.z, v.w);
    return make_uint2(*(uint32_t*)&h0, *(uint32_t*)&h1);
}

// ================= fp16 wmma GEMM: 256 thr, 8 warps (2x4), warp 64x32 =======
// (verified R10)
#define GH_LDS 72
#define GH_BUF (128*GH_LDS)
#define GH_LDE 132
#define GH_SMEM_BYTES (4*GH_BUF*2 > 128*GH_LDE*4 ? 4*GH_BUF*2 : 128*GH_LDE*4)

template<int ACT, int OUTMODE>
__global__ void __launch_bounds__(256, 2)
gemm_h(int M, int K,
       const __half* __restrict__ A, int lda,
       const __half* __restrict__ Bt, int ldb,
       const float* __restrict__ bias,
       float* __restrict__ Cf, __half* __restrict__ Ch, int ldc) {
    extern __shared__ __align__(128) __half smh[];
    const int tid = threadIdx.x;
    const int wid = tid >> 5;
    const int row0 = blockIdx.y * 128, col0 = blockIdx.x * 128;
    const int wm = wid & 1, wn = wid >> 1;

    wmma::fragment<wmma::accumulator, 16, 16, 16, float> acc[4][2];
#pragma unroll
    for (int i = 0; i < 4; i++)
#pragma unroll
        for (int j = 0; j < 2; j++) wmma::fill_fragment(acc[i][j], 0.f);

    const int nc = K >> 6;
    const int r = tid >> 3, c = tid & 7;

    {   // stage 0
        __half* As = smh;
        __half* Bs = smh + 2*GH_BUF;
#pragma unroll
        for (int i = 0; i < 4; i++) {
            int rr = r + i * 32;
            cp16(s2u(&As[rr * GH_LDS + c * 8]),
                 A + (size_t)(row0 + rr) * lda + c * 8, (row0 + rr) < M);
            cp16(s2u(&Bs[rr * GH_LDS + c * 8]),
                 Bt + (size_t)(col0 + rr) * ldb + c * 8, true);
        }
        CP_COMMIT();
    }

    for (int kc = 0; kc < nc; kc++) {
        const int cur = kc & 1;
        CP_WAIT0();
        __syncthreads();
        if (kc + 1 < nc) {
            const int nxt = 1 - cur;
            const int ko = (kc + 1) * 64;
            __half* As = smh + nxt * GH_BUF;
            __half* Bs = smh + 2*GH_BUF + nxt * GH_BUF;
#pragma unroll
            for (int i = 0; i < 4; i++) {
                int rr = r + i * 32;
                cp16(s2u(&As[rr * GH_LDS + c * 8]),
                     A + (size_t)(row0 + rr) * lda + ko + c * 8, (row0 + rr) < M);
                cp16(s2u(&Bs[rr * GH_LDS + c * 8]),
                     Bt + (size_t)(col0 + rr) * ldb + ko + c * 8, true);
            }
            CP_COMMIT();
        }
        const __half* As = smh + cur * GH_BUF;
        const __half* Bs = smh + 2*GH_BUF + cur * GH_BUF;
#pragma unroll
        for (int ks = 0; ks < 4; ks++) {
            wmma::fragment<wmma::matrix_a, 16, 16, 16, __half, wmma::row_major> af[4];
#pragma unroll
            for (int i = 0; i < 4; i++)
                wmma::load_matrix_sync(af[i], &As[(wm*64 + i*16) * GH_LDS + ks*16], GH_LDS);
#pragma unroll
            for (int j = 0; j < 2; j++) {
                wmma::fragment<wmma::matrix_b, 16, 16, 16, __half, wmma::col_major> bf;
                wmma::load_matrix_sync(bf, &Bs[(wn*32 + j*16) * GH_LDS + ks*16], GH_LDS);
#pragma unroll
                for (int i = 0; i < 4; i++)
                    wmma::mma_sync(acc[i][j], af[i], bf, acc[i][j]);
            }
        }
    }

    __syncthreads();
    float* Epi = (float*)smh;
#pragma unroll
    for (int i = 0; i < 4; i++)
#pragma unroll
        for (int j = 0; j < 2; j++)
            wmma::store_matrix_sync(&Epi[(wm*64 + i*16) * GH_LDE + wn*32 + j*16],
                                    acc[i][j], GH_LDE, wmma::mem_row_major);
    __syncthreads();
#pragma unroll 4
    for (int it = 0; it < 16; it++) {
        int l = it * 256 + tid;
        int rr = l >> 5, c4 = l & 31;
        int gr = row0 + rr;
        if (gr >= M) continue;
        float4 v = *(float4*)&Epi[rr * GH_LDE + c4 * 4];
        int gc = col0 + c4 * 4;
        v.x += bias[gc+0]; v.y += bias[gc+1]; v.z += bias[gc+2]; v.w += bias[gc+3];
        if (ACT == 1) {
            v.x = gelu_exact(v.x); v.y = gelu_exact(v.y);
            v.z = gelu_exact(v.z); v.w = gelu_exact(v.w);
        }
        if (OUTMODE == 2) {
            *(uint2*)(Ch + (size_t)gr * ldc + gc) = f4_to_h4(v);
        } else {
            float* cp = Cf + (size_t)gr * ldc + gc;
            if (OUTMODE == 1) {
                float4 o = *(const float4*)cp;
                v.x += o.x; v.y += o.y; v.z += o.z; v.w += o.w;
            }
            *(float4*)cp = v;
        }
    }
}

// ---------------- QKV projection (tf32 compute; half in/out, verified R15) --
__global__ void __launch_bounds__(128)
k_qkv_tc(const float* __restrict__ wq, const float* __restrict__ wk,
         const float* __restrict__ wv, const float* __restrict__ bq,
         const float* __restrict__ bk, const float* __restrict__ bv, int l) {
    __shared__ float Hs[64][68];
    __shared__ float Ws[64][68];
    __shared__ float Epi[64][68];
    int head = blockIdx.y, which = blockIdx.z;
    const float* W; const float* bias; __half* out;
    if (which == 0)      { W = wq; bias = bq; out = g_qh; }
    else if (which == 1) { W = wk; bias = bk; out = g_kh; }
    else                 { W = wv; bias = bv; out = g_vh; }
    W    += ((size_t)l*NHEAD + head) * DHEAD * DHEAD;
    bias += ((size_t)l*NHEAD + head) * DHEAD;
    const int m0 = blockIdx.x * 64;
    const int tid = threadIdx.x, wid = tid >> 5;

#pragma unroll
    for (int i = 0; i < 8; i++) {
        int ll = i * 128 + tid;
        int rr = ll >> 4, c4 = ll & 15;
        float4 v = make_float4(0.f,0.f,0.f,0.f);
        if (m0 + rr < MTOK) {
            uint2 raw = *(const uint2*)(g_hh + (size_t)(m0 + rr)*DIM + head*DHEAD + c4*4);
            v = h4_to_f4(raw);
        }
        *(float4*)&Hs[rr][c4*4] = v;
        float4 w = *(const float4*)(W + rr*64 + c4*4);
        w.x = r32(w.x); w.y = r32(w.y); w.z = r32(w.z); w.w = r32(w.w);
        *(float4*)&Ws[rr][c4*4] = w;
    }
    __syncthreads();

    wmma::fragment<wmma::accumulator, 16, 16, 8, float> acc[4];
#pragma unroll
    for (int j = 0; j < 4; j++) wmma::fill_fragment(acc[j], 0.f);
#pragma unroll
    for (int ks = 0; ks < 8; ks++) {
        wmma::fragment<wmma::matrix_a, 16, 16, 8, wmma::precision::tf32, wmma::row_major> af;
        wmma::load_matrix_sync(af, &Hs[wid*16][ks*8], 68);
#pragma unroll
        for (int j = 0; j < 4; j++) {
            wmma::fragment<wmma::matrix_b, 16, 16, 8, wmma::precision::tf32, wmma::row_major> bf;
            wmma::load_matrix_sync(bf, &Ws[ks*8][j*16], 68);
            wmma::mma_sync(acc[j], af, bf, acc[j]);
        }
    }
#pragma unroll
    for (int j = 0; j < 4; j++)
        wmma::store_matrix_sync(&Epi[wid*16][j*16], acc[j], 68, wmma::mem_row_major);
    __syncthreads();
#pragma unroll
    for (int i = 0; i < 8; i++) {
        int ll = i * 128 + tid;
        int rr = ll >> 4, c4 = ll & 15;
        int gr = m0 + rr;
        if (gr >= MTOK) continue;
        float4 v = *(float4*)&Epi[rr][c4*4];
        v.x += bias[c4*4+0]; v.y += bias[c4*4+1];
        v.z += bias[c4*4+2]; v.w += bias[c4*4+3];
        *(uint2*)(out + (size_t)gr*DIM + head*DHEAD + c4*4) = f4_to_h4(v);
    }
}

// ---------------- attention scores (tf32 compute; half in/out) --------------
__global__ void __launch_bounds__(128)
k_scores_tc() {
    __shared__ float Qs[64][68];
    __shared__ float Ks[64][68];
    __shared__ float Epi[64][68];
    const int bz = blockIdx.z;
    const int b = bz / NHEAD, h = bz % NHEAD;
    const int t0 = blockIdx.x * 64, s0 = blockIdx.y * 64;
    const int tid = threadIdx.x, wid = tid >> 5;
    const __half* Q = g_qh + (size_t)b*SEQ*DIM + h*DHEAD;
    const __half* K = g_kh + (size_t)b*SEQ*DIM + h*DHEAD;

#pragma unroll
    for (int i = 0; i < 8; i++) {
        int ll = i * 128 + tid;
        int rr = ll >> 4, c4 = ll & 15;
        float4 q = make_float4(0.f,0.f,0.f,0.f);
        if (s0 + rr < SEQ)
            q = h4_to_f4(*(const uint2*)(Q + (size_t)(s0 + rr)*DIM + c4*4));
        *(float4*)&Qs[rr][c4*4] = q;
        float4 k = make_float4(0.f,0.f,0.f,0.f);
        if (t0 + rr < SEQ)
            k = h4_to_f4(*(const uint2*)(K + (size_t)(t0 + rr)*DIM + c4*4));
        *(float4*)&Ks[rr][c4*4] = k;
    }
    __syncthreads();

    wmma::fragment<wmma::accumulator, 16, 16, 8, float> acc[4];
#pragma unroll
    for (int j = 0; j < 4; j++) wmma::fill_fragment(acc[j], 0.f);
#pragma unroll
    for (int ks = 0; ks < 8; ks++) {
        wmma::fragment<wmma::matrix_a, 16, 16, 8, wmma::precision::tf32, wmma::row_major> af;
        wmma::load_matrix_sync(af, &Qs[wid*16][ks*8], 68);
#pragma unroll
        for (int j = 0; j < 4; j++) {
            wmma::fragment<wmma::matrix_b, 16, 16, 8, wmma::precision::tf32, wmma::col_major> bf;
            wmma::load_matrix_sync(bf, &Ks[j*16][ks*8], 68);
            wmma::mma_sync(acc[j], af, bf, acc[j]);
        }
    }
#pragma unroll
    for (int j = 0; j < 4; j++)
        wmma::store_matrix_sync(&Epi[wid*16][j*16], acc[j], 68, wmma::mem_row_major);
    __syncthreads();
#pragma unroll
    for (int i = 0; i < 8; i++) {
        int ll = i * 128 + tid;
        int rr = ll >> 4, c4 = ll & 15;
        int s = s0 + rr;
        if (s >= SEQ) continue;
        int t = t0 + c4*4;
        if (t >= ASTRIDE) continue;
        float4 v = *(float4*)&Epi[rr][c4*4];
        v.x *= 0.125f; v.y *= 0.125f; v.z *= 0.125f; v.w *= 0.125f;
        __half* p = g_attnh + ((size_t)bz*SEQ + s)*ASTRIDE + t;
        if (t + 3 < SEQ) {
            *(uint2*)p = f4_to_h4(v);
        } else {
            float vv[4] = {v.x, v.y, v.z, v.w};
#pragma unroll
            for (int e = 0; e < 4; e++) {
                int tt = t + e;
                if (tt < ASTRIDE) p[e] = __float2half((tt < SEQ) ? vv[e] : 0.f);
            }
        }
    }
}

// ---------------- softmax: warp-per-row, half in/out ------------------------
__global__ void __launch_bounds__(256)
k_softmax_attn2() {
    int gw = blockIdx.x * 8 + (threadIdx.x >> 5);
    if (gw >= BATCH*NHEAD*SEQ) return;
    __half* p = g_attnh + (size_t)gw * ASTRIDE;
    int lane = threadIdx.x & 31;
    float v[7];
    float mx = -1e30f;
#pragma unroll
    for (int i = 0; i < 7; i++) {
        int t = lane + i*32;
        v[i] = (t < SEQ) ? __half2float(p[t]) : -1e30f;
        mx = fmaxf(mx, v[i]);
    }
#pragma unroll
    for (int o = 16; o > 0; o >>= 1) mx = fmaxf(mx, __shfl_xor_sync(0xffffffffu, mx, o));
    float sm = 0.f;
#pragma unroll
    for (int i = 0; i < 7; i++) {
        v[i] = (lane + i*32 < SEQ) ? expf(v[i] - mx) : 0.f;
        sm += v[i];
    }
#pragma unroll
    for (int o = 16; o > 0; o >>= 1) sm += __shfl_xor_sync(0xffffffffu, sm, o);
    float inv = 1.f / sm;
#pragma unroll
    for (int i = 0; i < 7; i++) {
        int t = lane + i*32;
        if (t < SEQ) p[t] = __float2half(v[i] * inv);
    }
}

// ---------------- o = attn @ v (tf32 compute; half in), fused residual -----
__global__ void __launch_bounds__(128)
k_av_tc() {
    __shared__ float Ps[64][20];
    __shared__ float Vs[16][68];
    __shared__ float Epi[64][68];
    const int bz = blockIdx.y;
    const int b = bz / NHEAD, h = bz % NHEAD;
    const int s0 = blockIdx.x * 64;
    const int tid = threadIdx.x, wid = tid >> 5;
    const __half* Pb = g_attnh + (size_t)bz*SEQ*ASTRIDE;
    const __half* V = g_vh + (size_t)b*SEQ*DIM + h*DHEAD;

    wmma::fragment<wmma::accumulator, 16, 16, 8, float> acc[4];
#pragma unroll
    for (int j = 0; j < 4; j++) wmma::fill_fragment(acc[j], 0.f);

    for (int kc = 0; kc < 13; kc++) {
#pragma unroll
        for (int i = 0; i < 2; i++) {
            int ll = i * 128 + tid;
            int rr = ll >> 2, cc = ll & 3;
            int s = s0 + rr;
            float4 pv = make_float4(0.f,0.f,0.f,0.f);
            if (s < SEQ)
                pv = h4_to_f4(*(const uint2*)(Pb + (size_t)s*ASTRIDE + kc*16 + cc*4));
            *(float4*)&Ps[rr][cc*4] = pv;
            int l2 = i * 128 + tid;
            int vr = l2 >> 4, vc = l2 & 15;
            int t = kc*16 + vr;
            float4 vv = make_float4(0.f,0.f,0.f,0.f);
            if (t < SEQ)
                vv = h4_to_f4(*(const uint2*)(V + (size_t)t*DIM + vc*4));
            *(float4*)&Vs[vr][vc*4] = vv;
        }
        __syncthreads();
#pragma unroll
        for (int ks = 0; ks < 2; ks++) {
            wmma::fragment<wmma::matrix_a, 16, 16, 8, wmma::precision::tf32, wmma::row_major> af;
            wmma::load_matrix_sync(af, &Ps[wid*16][ks*8], 20);
#pragma unroll
            for (int j = 0; j < 4; j++) {
                wmma::fragment<wmma::matrix_b, 16, 16, 8, wmma::precision::tf32, wmma::row_major> bf;
                wmma::load_matrix_sync(bf, &Vs[ks*8][j*16], 68);
                wmma::mma_sync(acc[j], af, bf, acc[j]);
            }
        }
        __syncthreads();
    }
#pragma unroll
    for (int j = 0; j < 4; j++)
        wmma::store_matrix_sync(&Epi[wid*16][j*16], acc[j], 68, wmma::mem_row_major);
    __syncthreads();
#pragma unroll
    for (int i = 0; i < 8; i++) {
        int ll = i * 128 + tid;
        int rr = ll >> 4, c4 = ll & 15;
        int s = s0 + rr;
        if (s >= SEQ) continue;
        float* tp = g_tokens + ((size_t)b*SEQ + s)*DIM + h*DHEAD + c4*4;
        float4 o = *(const float4*)tp;
        float4 v = *(float4*)&Epi[rr][c4*4];
        o.x += v.x; o.y += v.y; o.z += v.z; o.w += v.w;
        *(float4*)tp = o;
    }
}

// ---------------- transpose fp32 -> half [C,R] ------------------------------
__global__ void k_transpose_h(const float* __restrict__ in, __half* __restrict__ out,
                              int R, int C) {
    __shared__ float t[32][33];
    size_t lo = (size_t)blockIdx.z * R * C;
    int c0 = blockIdx.x * 32, r0 = blockIdx.y * 32;
#pragma unroll
    for (int i = 0; i < 4; i++) {
        int r = r0 + threadIdx.y + i * 8;
        int c = c0 + threadIdx.x;
        t[threadIdx.y + i * 8][threadIdx.x] = in[lo + (size_t)r * C + c];
    }
    __syncthreads();
#pragma unroll
    for (int i = 0; i < 4; i++) {
        int c = c0 + threadIdx.y + i * 8;
        int r = r0 + threadIdx.x;
        out[lo + (size_t)c * R + r] = __float2half(t[threadIdx.x][threadIdx.y + i * 8]);
    }
}

// ---------------- patchify (half out) ---------------------------------------
__global__ void k_patchify(const float* __restrict__ x, __half* __restrict__ out) {
    int idx = blockIdx.x * blockDim.x + threadIdx.x;
    const int total = MPAT * DIM;
    if (idx >= total) return;
    int e   = idx % DIM;
    int row = idx / DIM;
    int b  = row / NPATCH, p = row % NPATCH;
    int pi = p / 14, pj = p % 14;
    int c  = e / 256, r = e % 256;
    int ph = r / 16,  pw = r % 16;
    out[idx] = __float2half(x[(((b*3 + c)*224) + pi*16 + ph)*224 + pj*16 + pw]);
}

// ---------------- build tokens -----------------------------------------------
__global__ void k_build_tokens(const float* __restrict__ emb, const float* __restrict__ cls) {
    int idx = blockIdx.x * blockDim.x + threadIdx.x;
    if (idx >= MTOK * DIM) return;
    int d   = idx % DIM;
    int rem = idx / DIM;
    int s = rem % SEQ;
    int b = rem / SEQ;
    int jj = d & ~1;
    float p   = expf(-((float)jj / (float)DIM) * 9.210340371976184f);
    float arg = (float)s * p;
    float pe  = (d & 1) ? cosf(arg) : sinf(arg);
    float base = (s == 0) ? cls[d] : emb[(b*NPATCH + s - 1)*DIM + d];
    g_tokens[(size_t)b*SEQ*DIM + (size_t)s*DIM + d] = base + pe;
}

// ---------------- layernorm: writes half --------------------------------------
__global__ void k_layernorm(const float* __restrict__ in, const float* __restrict__ gam,
                            const float* __restrict__ bet,
                            float* __restrict__ outf, __half* __restrict__ outh) {
    int row = blockIdx.x;
    int tid = threadIdx.x;
    const float* xr = in + (size_t)row * DIM;
    float xs[3];
    float s = 0.f;
#pragma unroll
    for (int i = 0; i < 3; i++) { xs[i] = xr[tid + i*256]; s += xs[i]; }
    __shared__ float red[8];
#pragma unroll
    for (int o = 16; o > 0; o >>= 1) s += __shfl_xor_sync(0xffffffffu, s, o);
    if ((tid & 31) == 0) red[tid >> 5] = s;
    __syncthreads();
    float mu = 0.f;
    {
        float tot = 0.f;
#pragma unroll
        for (int i = 0; i < 8; i++) tot += red[i];
        mu = tot * (1.f / DIM);
    }
    __syncthreads();
    float v = 0.f;
#pragma unroll
    for (int i = 0; i < 3; i++) { float dlt = xs[i] - mu; v += dlt * dlt; }
#pragma unroll
    for (int o = 16; o > 0; o >>= 1) v += __shfl_xor_sync(0xffffffffu, v, o);
    if ((tid & 31) == 0) red[tid >> 5] = v;
    __syncthreads();
    float var = 0.f;
#pragma unroll
    for (int i = 0; i < 8; i++) var += red[i];
    var *= (1.f / DIM);
    float rstd = rsqrtf(var + 1e-5f);
#pragma unroll
    for (int i = 0; i < 3; i++) {
        int d = tid + i*256;
        float y = (xs[i] - mu) * rstd * gam[d] + bet[d];
        if (outf) outf[(size_t)row*DIM + d] = r32(y);
        if (outh) outh[(size_t)row*DIM + d] = __float2half(y);
    }
}

// ---------------- SIMT SGEMM (tiny head GEMM) ------------------------------
template<int ACT, bool ACCUM>
__global__ void sgemm128(int M, int N, int K,
                         const float* __restrict__ A, int lda,
                         const float* __restrict__ Bm, int ldb,
                         const float* __restrict__ bias,
                         float* __restrict__ C, int ldc) {
    __shared__ float As[8][128];
    __shared__ float Bs[8][132];
    int tid = threadIdx.x;
    int tx = tid & 15, ty = tid >> 4;
    int row0 = blockIdx.y * 128, col0 = blockIdx.x * 128;
    float acc[8][8];
#pragma unroll
    for (int i = 0; i < 8; i++)
#pragma unroll
        for (int j = 0; j < 8; j++) acc[i][j] = 0.f;

    for (int kk = 0; kk < K; kk += 8) {
        {
            int idx = tid * 4;
            int r = idx >> 3, c = idx & 7;
            float4 v = make_float4(0.f, 0.f, 0.f, 0.f);
            int gr = row0 + r;
            if (gr < M) v = *(const float4*)(A + (size_t)gr * lda + kk + c);
            As[c+0][r] = v.x; As[c+1][r] = v.y; As[c+2][r] = v.z; As[c+3][r] = v.w;
        }
        {
            int idx = tid * 4;
            int r = idx >> 7, c = idx & 127;
            int gc = col0 + c;
            float4 v;
            if (gc + 3 < N) {
                v = *(const float4*)(Bm + (size_t)(kk + r) * ldb + gc);
            } else {
                float t0 = (gc+0 < N) ? Bm[(size_t)(kk+r)*ldb + gc+0] : 0.f;
                float t1 = (gc+1 < N) ? Bm[(size_t)(kk+r)*ldb + gc+1] : 0.f;
                float t2 = (gc+2 < N) ? Bm[(size_t)(kk+r)*ldb + gc+2] : 0.f;
                float t3 = (gc+3 < N) ? Bm[(size_t)(kk+r)*ldb + gc+3] : 0.f;
                v = make_float4(t0, t1, t2, t3);
            }
            *(float4*)&Bs[r][c] = v;
        }
        __syncthreads();
#pragma unroll
        for (int k = 0; k < 8; k++) {
            float a[8], b[8];
            *(float4*)&a[0] = *(const float4*)&As[k][ty*8];
            *(float4*)&a[4] = *(const float4*)&As[k][ty*8 + 4];
            *(float4*)&b[0] = *(const float4*)&Bs[k][tx*8];
            *(float4*)&b[4] = *(const float4*)&Bs[k][tx*8 + 4];
#pragma unroll
            for (int i = 0; i < 8; i++)
#pragma unroll
                for (int j = 0; j < 8; j++)
                    acc[i][j] = fmaf(a[i], b[j], acc[i][j]);
        }
        __syncthreads();
    }
#pragma unroll
    for (int i = 0; i < 8; i++) {
        int gr = row0 + ty*8 + i;
        if (gr >= M) continue;
#pragma unroll
        for (int j = 0; j < 8; j++) {
            int gc = col0 + tx*8 + j;
            if (gc >= N) continue;
            float v = acc[i][j] + (bias ? bias[gc] : 0.f);
            if (ACT == 1) v = gelu_exact(v);
            if (ACCUM) C[(size_t)gr*ldc + gc] += v;
            else       C[(size_t)gr*ldc + gc]  = v;
        }
    }
}

// ---------------- output softmax --------------------------------------------
__global__ void k_softmax_out(const float* __restrict__ logits, float* __restrict__ out) {
    int row = blockIdx.x;
    int tid = threadIdx.x;
    const float* p = logits + (size_t)row * NOUT;
    float v[4];
    float mx = -1e30f;
#pragma unroll
    for (int i = 0; i < 4; i++) {
        int idx = tid + i*256;
        v[i] = (idx < NOUT) ? p[idx] : -1e30f;
        mx = fmaxf(mx, v[i]);
    }
    __shared__ float red[8];
#pragma unroll
    for (int o = 16; o > 0; o >>= 1) mx = fmaxf(mx, __shfl_xor_sync(0xffffffffu, mx, o));
    if ((tid & 31) == 0) red[tid >> 5] = mx;
    __syncthreads();
    float m2 = red[0];
#pragma unroll
    for (int i = 1; i < 8; i++) m2 = fmaxf(m2, red[i]);
    float e[4], sm = 0.f;
#pragma unroll
    for (int i = 0; i < 4; i++) {
        int idx = tid + i*256;
        e[i] = (idx < NOUT) ? expf(v[i] - m2) : 0.f;
        sm += e[i];
    }
#pragma unroll
    for (int o = 16; o > 0; o >>= 1) sm += __shfl_xor_sync(0xffffffffu, sm, o);
    __syncthreads();
    if ((tid & 31) == 0) red[tid >> 5] = sm;
    __syncthreads();
    float tot = 0.f;
#pragma unroll
    for (int i = 0; i < 8; i++) tot += red[i];
    float inv = 1.f / tot;
#pragma unroll
    for (int i = 0; i < 4; i++) {
        int idx = tid + i*256;
        if (idx < NOUT) out[(size_t)row*NOUT + idx] = e[i] * inv;
    }
}

// ============================ host launcher =================================
extern "C" void kernel_launch(void* const* d_in, const int* in_sizes, int n_in,
                              void* d_out, int out_size) {
    (void)in_sizes; (void)n_in; (void)out_size;
    const float* x       = (const float*)d_in[0];
    const float* w_embed = (const float*)d_in[1];
    const float* b_embed = (const float*)d_in[2];
    const float* cls     = (const float*)d_in[3];
    const float* ln1_g   = (const float*)d_in[4];
    const float* ln1_b   = (const float*)d_in[5];
    const float* wq      = (const float*)d_in[6];
    const float* bq      = (const float*)d_in[7];
    const float* wk      = (const float*)d_in[8];
    const float* bk      = (const float*)d_in[9];
    const float* wv      = (const float*)d_in[10];
    const float* bv      = (const float*)d_in[11];
    const float* ln2_g   = (const float*)d_in[12];
    const float* ln2_b   = (const float*)d_in[13];
    const float* w1      = (const float*)d_in[14];
    const float* b1      = (const float*)d_in[15];
    const float* w2      = (const float*)d_in[16];
    const float* b2      = (const float*)d_in[17];
    const float* w_head  = (const float*)d_in[18];
    const float* b_head  = (const float*)d_in[19];
    float* out = (float*)d_out;

    float *p_tokens, *p_embf;
    __half *p_hh, *p_mlph, *p_ph, *p_w1t, *p_w2t, *p_wembt;
    cudaGetSymbolAddress((void**)&p_tokens, g_tokens);
    cudaGetSymbolAddress((void**)&p_embf,   g_embf);
    cudaGetSymbolAddress((void**)&p_hh,     g_hh);
    cudaGetSymbolAddress((void**)&p_mlph,   g_mlph);
    cudaGetSymbolAddress((void**)&p_ph,     g_ph);
    cudaGetSymbolAddress((void**)&p_w1t,    g_w1t);
    cudaGetSymbolAddress((void**)&p_w2t,    g_w2t);
    cudaGetSymbolAddress((void**)&p_wembt,  g_wembt);

    cudaFuncSetAttribute(gemm_h<0,0>, cudaFuncAttributeMaxDynamicSharedMemorySize, GH_SMEM_BYTES);
    cudaFuncSetAttribute(gemm_h<1,2>, cudaFuncAttributeMaxDynamicSharedMemorySize, GH_SMEM_BYTES);
    cudaFuncSetAttribute(gemm_h<0,1>, cudaFuncAttributeMaxDynamicSharedMemorySize, GH_SMEM_BYTES);

    // ---- startup ----
    dim3 tb(32, 8);
    k_patchify<<<(MPAT*DIM + 255)/256, 256>>>(x, p_ph);
    k_transpose_h<<<dim3(DIM/32, DIM/32, 1), tb>>>(w_embed, p_wembt, DIM, DIM);
    k_transpose_h<<<dim3(MLPD/32, DIM/32, NLAYER), tb>>>(w1, p_w1t, DIM, MLPD);
    gemm_h<0,0><<<dim3(DIM/128, (MPAT+127)/128), 256, GH_SMEM_BYTES>>>(
        MPAT, DIM, p_ph, DIM, p_wembt, DIM, b_embed, p_embf, nullptr, DIM);
    k_transpose_h<<<dim3(DIM/32, MLPD/32, NLAYER), tb>>>(w2, p_w2t, MLPD, DIM);
    k_build_tokens<<<(MTOK*DIM + 255)/256, 256>>>(p_embf, cls);

    // ---- transformer layers ----
    const int softmax_rows = BATCH*NHEAD*SEQ;
    for (int l = 0; l < NLAYER; l++) {
        k_layernorm<<<MTOK, 256>>>(p_tokens, ln1_g + l*DIM, ln1_b + l*DIM, nullptr, p_hh);
        k_qkv_tc<<<dim3((MTOK + 63)/64, NHEAD, 3), 128>>>(wq, wk, wv, bq, bk, bv, l);
        k_scores_tc<<<dim3(4, 4, BATCH*NHEAD), 128>>>();
        k_softmax_attn2<<<(softmax_rows + 7)/8, 256>>>();
        k_av_tc<<<dim3(4, BATCH*NHEAD), 128>>>();
        k_layernorm<<<MTOK, 256>>>(p_tokens, ln2_g + l*DIM, ln2_b + l*DIM, nullptr, p_hh);
        gemm_h<1,2><<<dim3(MLPD/128, (MTOK+127)/128), 256, GH_SMEM_BYTES>>>(
            MTOK, DIM, p_hh, DIM, p_w1t + (size_t)l*MLPD*DIM, DIM,
            b1 + (size_t)l*MLPD, nullptr, p_mlph, MLPD);
        gemm_h<0,1><<<dim3(DIM/128, (MTOK+127)/128), 256, GH_SMEM_BYTES>>>(
            MTOK, MLPD, p_mlph, MLPD, p_w2t + (size_t)l*DIM*MLPD, MLPD,
            b2 + (size_t)l*DIM, p_tokens, nullptr, DIM);
    }

    // ---- classification head + softmax ----
    sgemm128<0, false><<<dim3(8, 1), 256>>>(BATCH, NOUT, DIM, p_tokens, SEQ*DIM,
                                            w_head, NOUT, b_head, p_embf, NOUT);
    k_softmax_out<<<BATCH, 256>>>(p_embf, out);
}